// round 10
// baseline (speedup 1.0000x reference)
#include <cuda_runtime.h>
#include <cstdint>
#include <math.h>

#define Bb 4
#define Nn 2048
#define Dd 512
#define Hh 8
#define HD 64
#define Mm (Bb * Nn)   // 8192
#define SC_LOG2E 0.18033688f   // 0.125 * log2(e)

// ---------------- scratch ----------------
__device__ float g_Q[(size_t)Mm * Dd];
__device__ float g_K[(size_t)Mm * Dd];
__device__ float g_V[(size_t)Mm * Dd];
__device__ float g_Hh[(size_t)Mm * Dd];
__device__ float g_Y[(size_t)Mm * Dd];

// ---------------- helpers ----------------
__device__ __forceinline__ uint32_t smem_u32(const void* p) {
    uint32_t a;
    asm("{ .reg .u64 t; cvta.to.shared.u64 t, %1; cvt.u32.u64 %0, t; }" : "=r"(a) : "l"(p));
    return a;
}
__device__ __forceinline__ float ex2(float x) {
    float y; asm("ex2.approx.f32 %0, %1;" : "=f"(y) : "f"(x)); return y;
}
__device__ __forceinline__ float tf32r(float f) {
    uint32_t u; asm("cvt.rna.tf32.f32 %0, %1;" : "=r"(u) : "f"(f));
    return __uint_as_float(u);
}
__device__ __forceinline__ float4 tf32r4(float4 v) {
    v.x = tf32r(v.x); v.y = tf32r(v.y); v.z = tf32r(v.z); v.w = tf32r(v.w);
    return v;
}
__device__ __forceinline__ void mma_tf32(float* c, const uint32_t* a, const uint32_t* b) {
    asm volatile("mma.sync.aligned.m16n8k8.row.col.f32.tf32.tf32.f32 "
        "{%0,%1,%2,%3}, {%4,%5,%6,%7}, {%8,%9}, {%0,%1,%2,%3};"
        : "+f"(c[0]), "+f"(c[1]), "+f"(c[2]), "+f"(c[3])
        : "r"(a[0]), "r"(a[1]), "r"(a[2]), "r"(a[3]), "r"(b[0]), "r"(b[1]));
}
__device__ __forceinline__ void ldsm4(uint32_t* r, uint32_t addr) {
    asm volatile("ldmatrix.sync.aligned.m8n8.x4.shared.b16 {%0,%1,%2,%3}, [%4];"
        : "=r"(r[0]), "=r"(r[1]), "=r"(r[2]), "=r"(r[3]) : "r"(addr));
}

// ======================================================================
// tf32 mma GEMM (R9 version, unchanged)
// ======================================================================
#define GBM 128
#define GBN 64
#define GBK 32
#define ASTR 36
#define BSTR 68

__global__ void __launch_bounds__(256, 3) gemm_mma_kernel(
    const float* __restrict__ A, const float* __restrict__ W,
    const float* __restrict__ bias, const float* __restrict__ resid,
    float* __restrict__ C, int M, int N, int K)
{
    __shared__ __align__(16) float As[GBM * ASTR];   // [m][k]
    __shared__ __align__(16) float Ws[GBK * BSTR];   // [k][n]

    const int tid = threadIdx.x;
    const int wid = tid >> 5, lane = tid & 31;
    const int g = lane >> 2, q = lane & 3;
    const int wm = wid & 3, wn = wid >> 2;
    const int m0 = blockIdx.y * GBM;
    const int n0 = blockIdx.x * GBN;

    float acc[2][4][4];
#pragma unroll
    for (int t = 0; t < 2; t++)
#pragma unroll
        for (int nb = 0; nb < 4; nb++)
#pragma unroll
            for (int i = 0; i < 4; i++) acc[t][nb][i] = 0.f;

    for (int k0 = 0; k0 < K; k0 += GBK) {
#pragma unroll
        for (int i = 0; i < 4; i++) {
            int idx = i * 256 + tid;
            int r = idx >> 3, c4 = (idx & 7) * 4;
            float4 a4 = tf32r4(*(const float4*)(A + (size_t)(m0 + r) * K + k0 + c4));
            *(float4*)(As + r * ASTR + c4) = a4;
        }
#pragma unroll
        for (int i = 0; i < 2; i++) {
            int idx = i * 256 + tid;
            int r = idx >> 4, c4 = (idx & 15) * 4;
            float4 w4 = tf32r4(*(const float4*)(W + (size_t)(k0 + r) * N + n0 + c4));
            *(float4*)(Ws + r * BSTR + c4) = w4;
        }
        __syncthreads();

#pragma unroll
        for (int kk = 0; kk < 4; kk++) {
            uint32_t a[2][4];
#pragma unroll
            for (int t = 0; t < 2; t++) {
                const float* ar = As + (wm * 32 + 16 * t + g) * ASTR + 8 * kk + q;
                a[t][0] = __float_as_uint(ar[0]);
                a[t][1] = __float_as_uint(ar[8 * ASTR]);
                a[t][2] = __float_as_uint(ar[4]);
                a[t][3] = __float_as_uint(ar[8 * ASTR + 4]);
            }
            uint32_t bf[4][2];
#pragma unroll
            for (int nb = 0; nb < 4; nb++) {
                const float* br = Ws + (8 * kk + q) * BSTR + wn * 32 + 8 * nb + g;
                bf[nb][0] = __float_as_uint(br[0]);
                bf[nb][1] = __float_as_uint(br[4 * BSTR]);
            }
#pragma unroll
            for (int t = 0; t < 2; t++)
#pragma unroll
                for (int nb = 0; nb < 4; nb++)
                    mma_tf32(acc[t][nb], a[t], bf[nb]);
        }
        __syncthreads();
    }

#pragma unroll
    for (int t = 0; t < 2; t++) {
        const int r0 = m0 + wm * 32 + 16 * t + g;
#pragma unroll
        for (int nb = 0; nb < 4; nb++) {
            const int c = n0 + wn * 32 + 8 * nb + 2 * q;
            float bx = bias[c], by = bias[c + 1];
            float2 w0, w1;
            w0.x = acc[t][nb][0] + bx; w0.y = acc[t][nb][1] + by;
            w1.x = acc[t][nb][2] + bx; w1.y = acc[t][nb][3] + by;
            if (resid) {
                float2 r4 = *(const float2*)(resid + (size_t)r0 * N + c);
                float2 r5 = *(const float2*)(resid + (size_t)(r0 + 8) * N + c);
                w0.x += r4.x; w0.y += r4.y;
                w1.x += r5.x; w1.y += r5.y;
            }
            *(float2*)(C + (size_t)r0 * N + c) = w0;
            *(float2*)(C + (size_t)(r0 + 8) * N + c) = w1;
        }
    }
}

// ======================================================================
// mma.sync tf32 attention (R9 structure + ldmatrix frag loads)
// 128 queries/CTA, 256 threads (8 warps), 16 queries/warp, 2 CTAs/SM.
// ======================================================================
#define STR 68
#define OFF_Q 0
#define OFF_K (128 * STR)
#define OFF_V (192 * STR)
#define OFF_P (256 * STR)
#define ATTN_SMEM_FLOATS (384 * STR)            // 26112
#define ATTN_SMEM_BYTES (ATTN_SMEM_FLOATS * 4)  // 104448

__global__ void __launch_bounds__(256, 2) attn_mma_kernel(
    const float* __restrict__ Q, const float* __restrict__ K,
    const float* __restrict__ V, const int* __restrict__ adj,
    float* __restrict__ O)
{
    extern __shared__ __align__(16) float sm[];
    const uint32_t sbase = smem_u32(sm);
    const int tid = threadIdx.x;
    const int wid = tid >> 5, lane = tid & 31;
    const int g = lane >> 2, q = lane & 3;
    const int h = blockIdx.y, b = blockIdx.z;
    const int q0 = blockIdx.x * 128;
    const unsigned FULL = 0xffffffffu;

    // ldmatrix per-lane row assignment
    const int lsub = lane & 7, mat = lane >> 3;
    // Q/P a-frag tiles: row = lsub + (mat&1)*8, col = (mat>>1)*4
    const uint32_t aQ = sbase + (uint32_t)(OFF_Q
        + (wid * 16 + lsub + (mat & 1) * 8) * STR + (mat >> 1) * 4) * 4u;
    const uint32_t aP = sbase + (uint32_t)(OFF_P
        + (wid * 16 + lsub + (mat & 1) * 8) * STR + (mat >> 1) * 4) * 4u;
    // K b-frag tiles (n-pair): row = lsub + (mat>>1)*8 (+16*np), col = (mat&1)*4
    const uint32_t aK = sbase + (uint32_t)(OFF_K
        + (lsub + (mat >> 1) * 8) * STR + (mat & 1) * 4) * 4u;

    // ---- stage Q tile (128 x 64), tf32-rounded ----
    {
        const float* qg = Q + ((size_t)(b * Nn + q0)) * Dd + h * HD;
#pragma unroll
        for (int i = 0; i < 8; i++) {
            int f = i * 256 + tid, r = f >> 4, c = (f & 15) * 4;
            float4 v4 = tf32r4(*(const float4*)(qg + (size_t)r * Dd + c));
            *(float4*)(sm + OFF_Q + r * STR + c) = v4;
        }
    }
    __syncthreads();

    float oacc[8][4];
#pragma unroll
    for (int n = 0; n < 8; n++)
#pragma unroll
        for (int i = 0; i < 4; i++) oacc[n][i] = 0.f;
    float lacc[2] = {0.f, 0.f};

    float* Pw = sm + OFF_P + wid * 16 * STR;
    const float* Vs = sm + OFF_V;

#pragma unroll 1
    for (int t64 = 0; t64 < 32; t64++) {
        const int k0 = t64 * 64;
        __syncthreads();
        // ---- stage K, V tiles (64 x 64), tf32-rounded ----
        {
            const float* kg = K + ((size_t)(b * Nn + k0)) * Dd + h * HD;
            const float* vg = V + ((size_t)(b * Nn + k0)) * Dd + h * HD;
#pragma unroll
            for (int i = 0; i < 4; i++) {
                int f = i * 256 + tid, r = f >> 4, c = (f & 15) * 4;
                float4 kv = tf32r4(*(const float4*)(kg + (size_t)r * Dd + c));
                *(float4*)(sm + OFF_K + r * STR + c) = kv;
                float4 vv = tf32r4(*(const float4*)(vg + (size_t)r * Dd + c));
                *(float4*)(sm + OFF_V + r * STR + c) = vv;
            }
        }
        __syncthreads();

        // ---- S = Q(16x64) @ K^T(64x64): ldmatrix frags, 64 mma ----
        float sacc[8][4];
#pragma unroll
        for (int n = 0; n < 8; n++)
#pragma unroll
            for (int i = 0; i < 4; i++) sacc[n][i] = 0.f;

#pragma unroll
        for (int kk = 0; kk < 8; kk++) {
            uint32_t a[4];
            ldsm4(a, aQ + kk * 32);
#pragma unroll
            for (int np = 0; np < 4; np++) {
                uint32_t kb[4];
                ldsm4(kb, aK + (uint32_t)(np * 16 * STR * 4) + kk * 32);
                mma_tf32(sacc[2 * np + 0], a, kb + 0);
                mma_tf32(sacc[2 * np + 1], a, kb + 2);
            }
        }

        // ---- softmax: P = mask * exp2(S*sc); row sums; store P ----
        {
            const size_t arow = (size_t)(b * Nn + q0 + wid * 16 + g) * Nn + k0;
            const int* a0p = adj + arow;                     // row g
            const int* a1p = adj + arow + (size_t)8 * Nn;    // row g+8
            float l0 = 0.f, l1 = 0.f;
#pragma unroll
            for (int n = 0; n < 8; n++) {
                int2 m0 = *(const int2*)(a0p + 8 * n + 2 * q);
                int2 m1 = *(const int2*)(a1p + 8 * n + 2 * q);
                float p0 = m0.x ? ex2(sacc[n][0] * SC_LOG2E) : 0.f;
                float p1 = m0.y ? ex2(sacc[n][1] * SC_LOG2E) : 0.f;
                float p2 = m1.x ? ex2(sacc[n][2] * SC_LOG2E) : 0.f;
                float p3 = m1.y ? ex2(sacc[n][3] * SC_LOG2E) : 0.f;
                l0 += p0 + p1; l1 += p2 + p3;
                float2 w0; w0.x = tf32r(p0); w0.y = tf32r(p1);
                float2 w1; w1.x = tf32r(p2); w1.y = tf32r(p3);
                *(float2*)(Pw + g * STR + 8 * n + 2 * q) = w0;
                *(float2*)(Pw + (g + 8) * STR + 8 * n + 2 * q) = w1;
            }
            lacc[0] += l0;
            lacc[1] += l1;
        }
        __syncwarp();

        // ---- O += P(16x64) @ V(64x64): P via ldmatrix, 64 mma ----
#pragma unroll
        for (int kk = 0; kk < 8; kk++) {
            uint32_t a[4];
            ldsm4(a, aP + kk * 32);
            uint32_t bf[8][2];
#pragma unroll
            for (int n = 0; n < 8; n++) {
                const float* vrow = Vs + (8 * kk + q) * STR + 8 * n + g;
                bf[n][0] = __float_as_uint(vrow[0]);
                bf[n][1] = __float_as_uint(vrow[4 * STR]);
            }
#pragma unroll
            for (int n = 0; n < 8; n++)
                mma_tf32(oacc[n], a, bf[n]);
        }
        __syncwarp();
    }

    // ---- reduce row sums across the quad ----
#pragma unroll
    for (int i = 0; i < 2; i++) {
        lacc[i] += __shfl_xor_sync(FULL, lacc[i], 1);
        lacc[i] += __shfl_xor_sync(FULL, lacc[i], 2);
    }
    const float inv0 = 1.f / lacc[0];
    const float inv1 = 1.f / lacc[1];

    // ---- write O ----
    float* og = O + ((size_t)(b * Nn + q0 + wid * 16)) * Dd + h * HD;
#pragma unroll
    for (int n = 0; n < 8; n++) {
        float2 w0;
        w0.x = oacc[n][0] * inv0;
        w0.y = oacc[n][1] * inv0;
        *(float2*)(og + (size_t)g * Dd + 8 * n + 2 * q) = w0;
        float2 w1;
        w1.x = oacc[n][2] * inv1;
        w1.y = oacc[n][3] * inv1;
        *(float2*)(og + (size_t)(g + 8) * Dd + 8 * n + 2 * q) = w1;
    }
}

// ================= LayerNorm (unchanged) =================
__global__ __launch_bounds__(128) void ln_kernel(
    const float* __restrict__ Y, const float* __restrict__ gamma,
    const float* __restrict__ beta, float* __restrict__ out)
{
    __shared__ float sbuf[4];
    __shared__ float smu, srstd;
    const int tid = threadIdx.x;
    const int row = blockIdx.x;
    const float* y = Y + (size_t)row * Dd;

    float4 v = ((const float4*)y)[tid];
    float sum = v.x + v.y + v.z + v.w;
    int lane = tid & 31, wid = tid >> 5;
#pragma unroll
    for (int off = 16; off > 0; off >>= 1) sum += __shfl_xor_sync(0xffffffffu, sum, off);
    if (lane == 0) sbuf[wid] = sum;
    __syncthreads();
    if (tid == 0) smu = (sbuf[0] + sbuf[1] + sbuf[2] + sbuf[3]) * (1.f / Dd);
    __syncthreads();
    float mu = smu;

    float dx = v.x - mu, dy = v.y - mu, dz = v.z - mu, dw = v.w - mu;
    float sq = dx * dx + dy * dy + dz * dz + dw * dw;
#pragma unroll
    for (int off = 16; off > 0; off >>= 1) sq += __shfl_xor_sync(0xffffffffu, sq, off);
    __syncthreads();
    if (lane == 0) sbuf[wid] = sq;
    __syncthreads();
    if (tid == 0) {
        float var = (sbuf[0] + sbuf[1] + sbuf[2] + sbuf[3]) * (1.f / Dd);
        srstd = rsqrtf(var + 1e-5f);
    }
    __syncthreads();
    float rstd = srstd;

    int c = tid * 4;
    float4 g = *(const float4*)(gamma + c);
    float4 be = *(const float4*)(beta + c);
    float4 r;
    r.x = dx * rstd * g.x + be.x;
    r.y = dy * rstd * g.y + be.y;
    r.z = dz * rstd * g.z + be.z;
    r.w = dw * rstd * g.w + be.w;
    ((float4*)(out + (size_t)row * Dd))[tid] = r;
}

// ================= launch =================
extern "C" void kernel_launch(void* const* d_in, const int* in_sizes, int n_in,
                              void* d_out, int out_size)
{
    const float* x     = (const float*)d_in[0];
    const int*   adj   = (const int*)d_in[1];
    const float* Wq    = (const float*)d_in[2];
    const float* bq    = (const float*)d_in[3];
    const float* Wk    = (const float*)d_in[4];
    const float* bk    = (const float*)d_in[5];
    const float* Wv    = (const float*)d_in[6];
    const float* bv    = (const float*)d_in[7];
    const float* Wo    = (const float*)d_in[8];
    const float* bo    = (const float*)d_in[9];
    const float* gamma = (const float*)d_in[10];
    const float* beta  = (const float*)d_in[11];
    float* out = (float*)d_out;

    float *Qb, *Kb, *Vb, *Hb, *Yb;
    cudaGetSymbolAddress((void**)&Qb, g_Q);
    cudaGetSymbolAddress((void**)&Kb, g_K);
    cudaGetSymbolAddress((void**)&Vb, g_V);
    cudaGetSymbolAddress((void**)&Hb, g_Hh);
    cudaGetSymbolAddress((void**)&Yb, g_Y);

    cudaFuncSetAttribute(attn_mma_kernel, cudaFuncAttributeMaxDynamicSharedMemorySize, ATTN_SMEM_BYTES);

    dim3 ggrid(Dd / GBN, Mm / GBM);   // (8, 64)
    gemm_mma_kernel<<<ggrid, 256>>>(x, Wq, bq, nullptr, Qb, Mm, Dd, Dd);
    gemm_mma_kernel<<<ggrid, 256>>>(x, Wk, bk, nullptr, Kb, Mm, Dd, Dd);
    gemm_mma_kernel<<<ggrid, 256>>>(x, Wv, bv, nullptr, Vb, Mm, Dd, Dd);

    dim3 agrid(Nn / 128, Hh, Bb);     // (16, 8, 4)
    attn_mma_kernel<<<agrid, 256, ATTN_SMEM_BYTES>>>(Qb, Kb, Vb, adj, Hb);

    gemm_mma_kernel<<<ggrid, 256>>>(Hb, Wo, bo, x, Yb, Mm, Dd, Dd);

    ln_kernel<<<Mm, 128>>>(Yb, gamma, beta, out);
}

// round 11
// speedup vs baseline: 1.0949x; 1.0949x over previous
#include <cuda_runtime.h>
#include <cstdint>
#include <math.h>

#define Bb 4
#define Nn 2048
#define Dd 512
#define Hh 8
#define HD 64
#define Mm (Bb * Nn)   // 8192
#define SC_LOG2E 0.18033688f   // 0.125 * log2(e)

// ---------------- scratch ----------------
__device__ float g_Q[(size_t)Mm * Dd];
__device__ float g_K[(size_t)Mm * Dd];
__device__ float g_V[(size_t)Mm * Dd];
__device__ float g_Hh[(size_t)Mm * Dd];
__device__ float g_Y[(size_t)Mm * Dd];

// ---------------- helpers ----------------
__device__ __forceinline__ uint32_t smem_u32(const void* p) {
    uint32_t a;
    asm("{ .reg .u64 t; cvta.to.shared.u64 t, %1; cvt.u32.u64 %0, t; }" : "=r"(a) : "l"(p));
    return a;
}
__device__ __forceinline__ float ex2(float x) {
    float y; asm("ex2.approx.f32 %0, %1;" : "=f"(y) : "f"(x)); return y;
}
__device__ __forceinline__ float tf32r(float f) {
    uint32_t u; asm("cvt.rna.tf32.f32 %0, %1;" : "=r"(u) : "f"(f));
    return __uint_as_float(u);
}
__device__ __forceinline__ float4 tf32r4(float4 v) {
    v.x = tf32r(v.x); v.y = tf32r(v.y); v.z = tf32r(v.z); v.w = tf32r(v.w);
    return v;
}
__device__ __forceinline__ void mma_tf32(float* c, const uint32_t* a, const uint32_t* b) {
    asm volatile("mma.sync.aligned.m16n8k8.row.col.f32.tf32.tf32.f32 "
        "{%0,%1,%2,%3}, {%4,%5,%6,%7}, {%8,%9}, {%0,%1,%2,%3};"
        : "+f"(c[0]), "+f"(c[1]), "+f"(c[2]), "+f"(c[3])
        : "r"(a[0]), "r"(a[1]), "r"(a[2]), "r"(a[3]), "r"(b[0]), "r"(b[1]));
}
__device__ __forceinline__ void cpa16(uint32_t dst, const void* src) {
    asm volatile("cp.async.cg.shared.global [%0], [%1], 16;" :: "r"(dst), "l"(src));
}
#define CP_COMMIT() asm volatile("cp.async.commit_group;" ::: "memory")
#define CP_WAIT1()  asm volatile("cp.async.wait_group 1;" ::: "memory")
#define CP_WAIT0()  asm volatile("cp.async.wait_group 0;" ::: "memory")

// ======================================================================
// tf32 mma GEMM (R9 version + roundOut epilogue flag)
// BM=128, BN=64, BK=32, 256 threads (8 warps 4x2), warp tile 32x32.
// ======================================================================
#define GBM 128
#define GBN 64
#define GBK 32
#define ASTR 36
#define BSTR 68

__global__ void __launch_bounds__(256, 3) gemm_mma_kernel(
    const float* __restrict__ A, const float* __restrict__ W,
    const float* __restrict__ bias, const float* __restrict__ resid,
    float* __restrict__ C, int M, int N, int K, int roundOut)
{
    __shared__ __align__(16) float As[GBM * ASTR];   // [m][k]
    __shared__ __align__(16) float Ws[GBK * BSTR];   // [k][n]

    const int tid = threadIdx.x;
    const int wid = tid >> 5, lane = tid & 31;
    const int g = lane >> 2, q = lane & 3;
    const int wm = wid & 3, wn = wid >> 2;
    const int m0 = blockIdx.y * GBM;
    const int n0 = blockIdx.x * GBN;

    float acc[2][4][4];
#pragma unroll
    for (int t = 0; t < 2; t++)
#pragma unroll
        for (int nb = 0; nb < 4; nb++)
#pragma unroll
            for (int i = 0; i < 4; i++) acc[t][nb][i] = 0.f;

    for (int k0 = 0; k0 < K; k0 += GBK) {
#pragma unroll
        for (int i = 0; i < 4; i++) {
            int idx = i * 256 + tid;
            int r = idx >> 3, c4 = (idx & 7) * 4;
            float4 a4 = tf32r4(*(const float4*)(A + (size_t)(m0 + r) * K + k0 + c4));
            *(float4*)(As + r * ASTR + c4) = a4;
        }
#pragma unroll
        for (int i = 0; i < 2; i++) {
            int idx = i * 256 + tid;
            int r = idx >> 4, c4 = (idx & 15) * 4;
            float4 w4 = tf32r4(*(const float4*)(W + (size_t)(k0 + r) * N + n0 + c4));
            *(float4*)(Ws + r * BSTR + c4) = w4;
        }
        __syncthreads();

#pragma unroll
        for (int kk = 0; kk < 4; kk++) {
            uint32_t a[2][4];
#pragma unroll
            for (int t = 0; t < 2; t++) {
                const float* ar = As + (wm * 32 + 16 * t + g) * ASTR + 8 * kk + q;
                a[t][0] = __float_as_uint(ar[0]);
                a[t][1] = __float_as_uint(ar[8 * ASTR]);
                a[t][2] = __float_as_uint(ar[4]);
                a[t][3] = __float_as_uint(ar[8 * ASTR + 4]);
            }
            uint32_t bf[4][2];
#pragma unroll
            for (int nb = 0; nb < 4; nb++) {
                const float* br = Ws + (8 * kk + q) * BSTR + wn * 32 + 8 * nb + g;
                bf[nb][0] = __float_as_uint(br[0]);
                bf[nb][1] = __float_as_uint(br[4 * BSTR]);
            }
#pragma unroll
            for (int t = 0; t < 2; t++)
#pragma unroll
                for (int nb = 0; nb < 4; nb++)
                    mma_tf32(acc[t][nb], a[t], bf[nb]);
        }
        __syncthreads();
    }

#pragma unroll
    for (int t = 0; t < 2; t++) {
        const int r0 = m0 + wm * 32 + 16 * t + g;
#pragma unroll
        for (int nb = 0; nb < 4; nb++) {
            const int c = n0 + wn * 32 + 8 * nb + 2 * q;
            float bx = bias[c], by = bias[c + 1];
            float2 w0, w1;
            w0.x = acc[t][nb][0] + bx; w0.y = acc[t][nb][1] + by;
            w1.x = acc[t][nb][2] + bx; w1.y = acc[t][nb][3] + by;
            if (resid) {
                float2 r4 = *(const float2*)(resid + (size_t)r0 * N + c);
                float2 r5 = *(const float2*)(resid + (size_t)(r0 + 8) * N + c);
                w0.x += r4.x; w0.y += r4.y;
                w1.x += r5.x; w1.y += r5.y;
            }
            if (roundOut) {
                w0.x = tf32r(w0.x); w0.y = tf32r(w0.y);
                w1.x = tf32r(w1.x); w1.y = tf32r(w1.y);
            }
            *(float2*)(C + (size_t)r0 * N + c) = w0;
            *(float2*)(C + (size_t)(r0 + 8) * N + c) = w1;
        }
    }
}

// ======================================================================
// mma.sync tf32 attention (R9 frag paths + cp.async rotating pipeline)
// 128 queries/CTA, 256 threads (8 warps), 16 queries/warp, 2 CTAs/SM.
// Q/K/V arrive tf32-rounded (gemm roundOut); cp.async copies raw.
// ======================================================================
#define STR 68
#define OFF_Q 0
#define OFF_K (128 * STR)
#define OFF_V (192 * STR)
#define OFF_P (256 * STR)
#define ATTN_SMEM_FLOATS (384 * STR)            // 26112
#define ATTN_SMEM_BYTES (ATTN_SMEM_FLOATS * 4)  // 104448

__global__ void __launch_bounds__(256, 2) attn_mma_kernel(
    const float* __restrict__ Q, const float* __restrict__ K,
    const float* __restrict__ V, const int* __restrict__ adj,
    float* __restrict__ O)
{
    extern __shared__ __align__(16) float sm[];
    const uint32_t sbase = smem_u32(sm);
    const int tid = threadIdx.x;
    const int wid = tid >> 5, lane = tid & 31;
    const int g = lane >> 2, q = lane & 3;
    const int h = blockIdx.y, b = blockIdx.z;
    const int q0 = blockIdx.x * 128;
    const unsigned FULL = 0xffffffffu;

    const int fr = tid >> 4, fc = (tid & 15) * 4;   // 16 rows per 256-thread pass

    const float* kgbase = K + ((size_t)(b * Nn)) * Dd + h * HD;
    const float* vgbase = V + ((size_t)(b * Nn)) * Dd + h * HD;

    // ---- prologue: Q (group), K0 (group), V0 (group) via cp.async ----
    {
        const float* qg = Q + ((size_t)(b * Nn + q0)) * Dd + h * HD;
#pragma unroll
        for (int i = 0; i < 8; i++) {
            int r = i * 16 + fr;
            cpa16(sbase + (uint32_t)(OFF_Q + r * STR + fc) * 4, qg + (size_t)r * Dd + fc);
        }
        CP_COMMIT();
#pragma unroll
        for (int i = 0; i < 4; i++) {
            int r = i * 16 + fr;
            cpa16(sbase + (uint32_t)(OFF_K + r * STR + fc) * 4, kgbase + (size_t)r * Dd + fc);
        }
        CP_COMMIT();
#pragma unroll
        for (int i = 0; i < 4; i++) {
            int r = i * 16 + fr;
            cpa16(sbase + (uint32_t)(OFF_V + r * STR + fc) * 4, vgbase + (size_t)r * Dd + fc);
        }
        CP_COMMIT();
    }
    CP_WAIT1();          // Q + K0 complete; V0 may be in flight
    __syncthreads();

    float oacc[8][4];
#pragma unroll
    for (int n = 0; n < 8; n++)
#pragma unroll
        for (int i = 0; i < 4; i++) oacc[n][i] = 0.f;
    float lacc[2] = {0.f, 0.f};

    float* Pw = sm + OFF_P + wid * 16 * STR;
    const float* Ks = sm + OFF_K;
    const float* Vs = sm + OFF_V;

#pragma unroll 1
    for (int t64 = 0; t64 < 32; t64++) {
        const int k0 = t64 * 64;

        // ---- S = Q(16x64) @ K^T(64x64) per warp: 64 mma ----
        float sacc[8][4];
#pragma unroll
        for (int n = 0; n < 8; n++)
#pragma unroll
            for (int i = 0; i < 4; i++) sacc[n][i] = 0.f;

#pragma unroll
        for (int kk = 0; kk < 8; kk++) {
            uint32_t a[4];
            {
                const float* qrow = sm + OFF_Q + (wid * 16 + g) * STR + 8 * kk + q;
                a[0] = __float_as_uint(qrow[0]);
                a[1] = __float_as_uint(qrow[8 * STR]);
                a[2] = __float_as_uint(qrow[4]);
                a[3] = __float_as_uint(qrow[8 * STR + 4]);
            }
            uint32_t bf[8][2];
#pragma unroll
            for (int n = 0; n < 8; n++) {
                const float* krow = Ks + (8 * n + g) * STR + 8 * kk + q;
                bf[n][0] = __float_as_uint(krow[0]);
                bf[n][1] = __float_as_uint(krow[4]);
            }
#pragma unroll
            for (int n = 0; n < 8; n++)
                mma_tf32(sacc[n], a, bf[n]);
        }

        __syncthreads();   // all warps done reading K[t]
        if (t64 + 1 < 32) {
            const float* kg = kgbase + (size_t)(k0 + 64) * Dd;
#pragma unroll
            for (int i = 0; i < 4; i++) {
                int r = i * 16 + fr;
                cpa16(sbase + (uint32_t)(OFF_K + r * STR + fc) * 4, kg + (size_t)r * Dd + fc);
            }
            CP_COMMIT();   // outstanding: V[t], K[t+1]
        }

        // ---- softmax: P = mask * exp2(S*sc); row sums; store P ----
        {
            const size_t arow = (size_t)(b * Nn + q0 + wid * 16 + g) * Nn + k0;
            const int* a0p = adj + arow;                     // row g
            const int* a1p = adj + arow + (size_t)8 * Nn;    // row g+8
            float l0 = 0.f, l1 = 0.f;
#pragma unroll
            for (int n = 0; n < 8; n++) {
                int2 m0 = *(const int2*)(a0p + 8 * n + 2 * q);
                int2 m1 = *(const int2*)(a1p + 8 * n + 2 * q);
                float p0 = m0.x ? ex2(sacc[n][0] * SC_LOG2E) : 0.f;
                float p1 = m0.y ? ex2(sacc[n][1] * SC_LOG2E) : 0.f;
                float p2 = m1.x ? ex2(sacc[n][2] * SC_LOG2E) : 0.f;
                float p3 = m1.y ? ex2(sacc[n][3] * SC_LOG2E) : 0.f;
                l0 += p0 + p1; l1 += p2 + p3;
                float2 w0; w0.x = tf32r(p0); w0.y = tf32r(p1);
                float2 w1; w1.x = tf32r(p2); w1.y = tf32r(p3);
                *(float2*)(Pw + g * STR + 8 * n + 2 * q) = w0;
                *(float2*)(Pw + (g + 8) * STR + 8 * n + 2 * q) = w1;
            }
            lacc[0] += l0;
            lacc[1] += l1;
        }

        if (t64 + 1 < 32) CP_WAIT1();   // V[t] (oldest) complete
        else              CP_WAIT0();
        __syncthreads();                // V[t] visible; P visible within warp below

        // ---- O += P(16x64) @ V(64x64): 64 mma ----
#pragma unroll
        for (int kk = 0; kk < 8; kk++) {
            uint32_t a[4];
            {
                const float* prow = Pw + g * STR + 8 * kk + q;
                a[0] = __float_as_uint(prow[0]);
                a[1] = __float_as_uint(prow[8 * STR]);
                a[2] = __float_as_uint(prow[4]);
                a[3] = __float_as_uint(prow[8 * STR + 4]);
            }
            uint32_t bf[8][2];
#pragma unroll
            for (int n = 0; n < 8; n++) {
                const float* vrow = Vs + (8 * kk + q) * STR + 8 * n + g;
                bf[n][0] = __float_as_uint(vrow[0]);
                bf[n][1] = __float_as_uint(vrow[4 * STR]);
            }
#pragma unroll
            for (int n = 0; n < 8; n++)
                mma_tf32(oacc[n], a, bf[n]);
        }

        if (t64 + 1 < 32) {
            __syncthreads();   // all warps done reading V[t]
            const float* vg = vgbase + (size_t)(k0 + 64) * Dd;
#pragma unroll
            for (int i = 0; i < 4; i++) {
                int r = i * 16 + fr;
                cpa16(sbase + (uint32_t)(OFF_V + r * STR + fc) * 4, vg + (size_t)r * Dd + fc);
            }
            CP_COMMIT();       // outstanding: K[t+1], V[t+1]
            CP_WAIT1();        // K[t+1] complete
            __syncthreads();   // K[t+1] visible
        }
    }

    // ---- reduce row sums across the quad ----
#pragma unroll
    for (int i = 0; i < 2; i++) {
        lacc[i] += __shfl_xor_sync(FULL, lacc[i], 1);
        lacc[i] += __shfl_xor_sync(FULL, lacc[i], 2);
    }
    const float inv0 = 1.f / lacc[0];
    const float inv1 = 1.f / lacc[1];

    // ---- write O ----
    float* og = O + ((size_t)(b * Nn + q0 + wid * 16)) * Dd + h * HD;
#pragma unroll
    for (int n = 0; n < 8; n++) {
        float2 w0;
        w0.x = oacc[n][0] * inv0;
        w0.y = oacc[n][1] * inv0;
        *(float2*)(og + (size_t)g * Dd + 8 * n + 2 * q) = w0;
        float2 w1;
        w1.x = oacc[n][2] * inv1;
        w1.y = oacc[n][3] * inv1;
        *(float2*)(og + (size_t)(g + 8) * Dd + 8 * n + 2 * q) = w1;
    }
}

// ================= LayerNorm (unchanged) =================
__global__ __launch_bounds__(128) void ln_kernel(
    const float* __restrict__ Y, const float* __restrict__ gamma,
    const float* __restrict__ beta, float* __restrict__ out)
{
    __shared__ float sbuf[4];
    __shared__ float smu, srstd;
    const int tid = threadIdx.x;
    const int row = blockIdx.x;
    const float* y = Y + (size_t)row * Dd;

    float4 v = ((const float4*)y)[tid];
    float sum = v.x + v.y + v.z + v.w;
    int lane = tid & 31, wid = tid >> 5;
#pragma unroll
    for (int off = 16; off > 0; off >>= 1) sum += __shfl_xor_sync(0xffffffffu, sum, off);
    if (lane == 0) sbuf[wid] = sum;
    __syncthreads();
    if (tid == 0) smu = (sbuf[0] + sbuf[1] + sbuf[2] + sbuf[3]) * (1.f / Dd);
    __syncthreads();
    float mu = smu;

    float dx = v.x - mu, dy = v.y - mu, dz = v.z - mu, dw = v.w - mu;
    float sq = dx * dx + dy * dy + dz * dz + dw * dw;
#pragma unroll
    for (int off = 16; off > 0; off >>= 1) sq += __shfl_xor_sync(0xffffffffu, sq, off);
    __syncthreads();
    if (lane == 0) sbuf[wid] = sq;
    __syncthreads();
    if (tid == 0) {
        float var = (sbuf[0] + sbuf[1] + sbuf[2] + sbuf[3]) * (1.f / Dd);
        srstd = rsqrtf(var + 1e-5f);
    }
    __syncthreads();
    float rstd = srstd;

    int c = tid * 4;
    float4 g = *(const float4*)(gamma + c);
    float4 be = *(const float4*)(beta + c);
    float4 r;
    r.x = dx * rstd * g.x + be.x;
    r.y = dy * rstd * g.y + be.y;
    r.z = dz * rstd * g.z + be.z;
    r.w = dw * rstd * g.w + be.w;
    ((float4*)(out + (size_t)row * Dd))[tid] = r;
}

// ================= launch =================
extern "C" void kernel_launch(void* const* d_in, const int* in_sizes, int n_in,
                              void* d_out, int out_size)
{
    const float* x     = (const float*)d_in[0];
    const int*   adj   = (const int*)d_in[1];
    const float* Wq    = (const float*)d_in[2];
    const float* bq    = (const float*)d_in[3];
    const float* Wk    = (const float*)d_in[4];
    const float* bk    = (const float*)d_in[5];
    const float* Wv    = (const float*)d_in[6];
    const float* bv    = (const float*)d_in[7];
    const float* Wo    = (const float*)d_in[8];
    const float* bo    = (const float*)d_in[9];
    const float* gamma = (const float*)d_in[10];
    const float* beta  = (const float*)d_in[11];
    float* out = (float*)d_out;

    float *Qb, *Kb, *Vb, *Hb, *Yb;
    cudaGetSymbolAddress((void**)&Qb, g_Q);
    cudaGetSymbolAddress((void**)&Kb, g_K);
    cudaGetSymbolAddress((void**)&Vb, g_V);
    cudaGetSymbolAddress((void**)&Hb, g_Hh);
    cudaGetSymbolAddress((void**)&Yb, g_Y);

    cudaFuncSetAttribute(attn_mma_kernel, cudaFuncAttributeMaxDynamicSharedMemorySize, ATTN_SMEM_BYTES);

    dim3 ggrid(Dd / GBN, Mm / GBM);   // (8, 64)
    gemm_mma_kernel<<<ggrid, 256>>>(x, Wq, bq, nullptr, Qb, Mm, Dd, Dd, 1);
    gemm_mma_kernel<<<ggrid, 256>>>(x, Wk, bk, nullptr, Kb, Mm, Dd, Dd, 1);
    gemm_mma_kernel<<<ggrid, 256>>>(x, Wv, bv, nullptr, Vb, Mm, Dd, Dd, 1);

    dim3 agrid(Nn / 128, Hh, Bb);     // (16, 8, 4)
    attn_mma_kernel<<<agrid, 256, ATTN_SMEM_BYTES>>>(Qb, Kb, Vb, adj, Hb);

    gemm_mma_kernel<<<ggrid, 256>>>(Hb, Wo, bo, x, Yb, Mm, Dd, Dd, 0);

    ln_kernel<<<Mm, 128>>>(Yb, gamma, beta, out);
}

// round 12
// speedup vs baseline: 1.1512x; 1.0514x over previous
#include <cuda_runtime.h>
#include <cstdint>
#include <math.h>

#define Bb 4
#define Nn 2048
#define Dd 512
#define Hh 8
#define HD 64
#define Mm (Bb * Nn)   // 8192
#define NW (Nn / 32)   // 64 mask words per row
#define SC_LOG2E 0.18033688f   // 0.125 * log2(e)

// ---------------- scratch ----------------
__device__ float g_Q[(size_t)Mm * Dd];
__device__ float g_K[(size_t)Mm * Dd];
__device__ float g_V[(size_t)Mm * Dd];
__device__ float g_Hh[(size_t)Mm * Dd];
__device__ float g_Y[(size_t)Mm * Dd];
__device__ uint32_t g_Mb[(size_t)Mm * NW];   // bit-packed adjacency

// ---------------- helpers ----------------
__device__ __forceinline__ uint32_t smem_u32(const void* p) {
    uint32_t a;
    asm("{ .reg .u64 t; cvta.to.shared.u64 t, %1; cvt.u32.u64 %0, t; }" : "=r"(a) : "l"(p));
    return a;
}
__device__ __forceinline__ float ex2(float x) {
    float y; asm("ex2.approx.f32 %0, %1;" : "=f"(y) : "f"(x)); return y;
}
__device__ __forceinline__ float tf32r(float f) {
    uint32_t u; asm("cvt.rna.tf32.f32 %0, %1;" : "=r"(u) : "f"(f));
    return __uint_as_float(u);
}
__device__ __forceinline__ float4 tf32r4(float4 v) {
    v.x = tf32r(v.x); v.y = tf32r(v.y); v.z = tf32r(v.z); v.w = tf32r(v.w);
    return v;
}
__device__ __forceinline__ void mma_tf32(float* c, const uint32_t* a, const uint32_t* b) {
    asm volatile("mma.sync.aligned.m16n8k8.row.col.f32.tf32.tf32.f32 "
        "{%0,%1,%2,%3}, {%4,%5,%6,%7}, {%8,%9}, {%0,%1,%2,%3};"
        : "+f"(c[0]), "+f"(c[1]), "+f"(c[2]), "+f"(c[3])
        : "r"(a[0]), "r"(a[1]), "r"(a[2]), "r"(a[3]), "r"(b[0]), "r"(b[1]));
}
__device__ __forceinline__ void cpa16(uint32_t dst, const void* src) {
    asm volatile("cp.async.cg.shared.global [%0], [%1], 16;" :: "r"(dst), "l"(src));
}
#define CP_COMMIT() asm volatile("cp.async.commit_group;" ::: "memory")
#define CP_WAIT1()  asm volatile("cp.async.wait_group 1;" ::: "memory")
#define CP_WAIT0()  asm volatile("cp.async.wait_group 0;" ::: "memory")

// ---------------- mask bit-pack: one uint32 word per thread ----------------
__global__ void __launch_bounds__(256) pack_mask_kernel(
    const int* __restrict__ adj, uint32_t* __restrict__ mb)
{
    int idx = blockIdx.x * 256 + threadIdx.x;   // word index
    const int4* src = (const int4*)(adj + (size_t)idx * 32);
    uint32_t w = 0;
#pragma unroll
    for (int i = 0; i < 8; i++) {
        int4 v = src[i];
        w |= (v.x != 0 ? 1u : 0u) << (4 * i + 0);
        w |= (v.y != 0 ? 1u : 0u) << (4 * i + 1);
        w |= (v.z != 0 ? 1u : 0u) << (4 * i + 2);
        w |= (v.w != 0 ? 1u : 0u) << (4 * i + 3);
    }
    mb[idx] = w;
}

// ======================================================================
// tf32 mma GEMM (R11 version, unchanged)
// ======================================================================
#define GBM 128
#define GBN 64
#define GBK 32
#define ASTR 36
#define BSTR 68

__global__ void __launch_bounds__(256, 3) gemm_mma_kernel(
    const float* __restrict__ A, const float* __restrict__ W,
    const float* __restrict__ bias, const float* __restrict__ resid,
    float* __restrict__ C, int M, int N, int K, int roundOut)
{
    __shared__ __align__(16) float As[GBM * ASTR];   // [m][k]
    __shared__ __align__(16) float Ws[GBK * BSTR];   // [k][n]

    const int tid = threadIdx.x;
    const int wid = tid >> 5, lane = tid & 31;
    const int g = lane >> 2, q = lane & 3;
    const int wm = wid & 3, wn = wid >> 2;
    const int m0 = blockIdx.y * GBM;
    const int n0 = blockIdx.x * GBN;

    float acc[2][4][4];
#pragma unroll
    for (int t = 0; t < 2; t++)
#pragma unroll
        for (int nb = 0; nb < 4; nb++)
#pragma unroll
            for (int i = 0; i < 4; i++) acc[t][nb][i] = 0.f;

    for (int k0 = 0; k0 < K; k0 += GBK) {
#pragma unroll
        for (int i = 0; i < 4; i++) {
            int idx = i * 256 + tid;
            int r = idx >> 3, c4 = (idx & 7) * 4;
            float4 a4 = tf32r4(*(const float4*)(A + (size_t)(m0 + r) * K + k0 + c4));
            *(float4*)(As + r * ASTR + c4) = a4;
        }
#pragma unroll
        for (int i = 0; i < 2; i++) {
            int idx = i * 256 + tid;
            int r = idx >> 4, c4 = (idx & 15) * 4;
            float4 w4 = tf32r4(*(const float4*)(W + (size_t)(k0 + r) * N + n0 + c4));
            *(float4*)(Ws + r * BSTR + c4) = w4;
        }
        __syncthreads();

#pragma unroll
        for (int kk = 0; kk < 4; kk++) {
            uint32_t a[2][4];
#pragma unroll
            for (int t = 0; t < 2; t++) {
                const float* ar = As + (wm * 32 + 16 * t + g) * ASTR + 8 * kk + q;
                a[t][0] = __float_as_uint(ar[0]);
                a[t][1] = __float_as_uint(ar[8 * ASTR]);
                a[t][2] = __float_as_uint(ar[4]);
                a[t][3] = __float_as_uint(ar[8 * ASTR + 4]);
            }
            uint32_t bf[4][2];
#pragma unroll
            for (int nb = 0; nb < 4; nb++) {
                const float* br = Ws + (8 * kk + q) * BSTR + wn * 32 + 8 * nb + g;
                bf[nb][0] = __float_as_uint(br[0]);
                bf[nb][1] = __float_as_uint(br[4 * BSTR]);
            }
#pragma unroll
            for (int t = 0; t < 2; t++)
#pragma unroll
                for (int nb = 0; nb < 4; nb++)
                    mma_tf32(acc[t][nb], a[t], bf[nb]);
        }
        __syncthreads();
    }

#pragma unroll
    for (int t = 0; t < 2; t++) {
        const int r0 = m0 + wm * 32 + 16 * t + g;
#pragma unroll
        for (int nb = 0; nb < 4; nb++) {
            const int c = n0 + wn * 32 + 8 * nb + 2 * q;
            float bx = bias[c], by = bias[c + 1];
            float2 w0, w1;
            w0.x = acc[t][nb][0] + bx; w0.y = acc[t][nb][1] + by;
            w1.x = acc[t][nb][2] + bx; w1.y = acc[t][nb][3] + by;
            if (resid) {
                float2 r4 = *(const float2*)(resid + (size_t)r0 * N + c);
                float2 r5 = *(const float2*)(resid + (size_t)(r0 + 8) * N + c);
                w0.x += r4.x; w0.y += r4.y;
                w1.x += r5.x; w1.y += r5.y;
            }
            if (roundOut) {
                w0.x = tf32r(w0.x); w0.y = tf32r(w0.y);
                w1.x = tf32r(w1.x); w1.y = tf32r(w1.y);
            }
            *(float2*)(C + (size_t)r0 * N + c) = w0;
            *(float2*)(C + (size_t)(r0 + 8) * N + c) = w1;
        }
    }
}

// ======================================================================
// mma.sync tf32 attention (R11 pipeline + bit-packed masks)
// 128 queries/CTA, 256 threads (8 warps), 16 queries/warp, 2 CTAs/SM.
// ======================================================================
#define STR 68
#define OFF_Q 0
#define OFF_K (128 * STR)
#define OFF_V (192 * STR)
#define OFF_P (256 * STR)
#define ATTN_SMEM_FLOATS (384 * STR)            // 26112
#define ATTN_SMEM_BYTES (ATTN_SMEM_FLOATS * 4)  // 104448

__global__ void __launch_bounds__(256, 2) attn_mma_kernel(
    const float* __restrict__ Q, const float* __restrict__ K,
    const float* __restrict__ V, const uint32_t* __restrict__ mb,
    float* __restrict__ O)
{
    extern __shared__ __align__(16) float sm[];
    const uint32_t sbase = smem_u32(sm);
    const int tid = threadIdx.x;
    const int wid = tid >> 5, lane = tid & 31;
    const int g = lane >> 2, q = lane & 3;
    const int h = blockIdx.y, b = blockIdx.z;
    const int q0 = blockIdx.x * 128;
    const unsigned FULL = 0xffffffffu;

    const int fr = tid >> 4, fc = (tid & 15) * 4;   // 16 rows per 256-thread pass

    const float* kgbase = K + ((size_t)(b * Nn)) * Dd + h * HD;
    const float* vgbase = V + ((size_t)(b * Nn)) * Dd + h * HD;
    // packed mask rows for this lane's two query rows
    const uint32_t* mrow0 = mb + (size_t)(b * Nn + q0 + wid * 16 + g) * NW;
    const uint32_t* mrow1 = mrow0 + (size_t)8 * NW;

    // ---- prologue: Q (group), K0 (group), V0 (group) via cp.async ----
    {
        const float* qg = Q + ((size_t)(b * Nn + q0)) * Dd + h * HD;
#pragma unroll
        for (int i = 0; i < 8; i++) {
            int r = i * 16 + fr;
            cpa16(sbase + (uint32_t)(OFF_Q + r * STR + fc) * 4, qg + (size_t)r * Dd + fc);
        }
        CP_COMMIT();
#pragma unroll
        for (int i = 0; i < 4; i++) {
            int r = i * 16 + fr;
            cpa16(sbase + (uint32_t)(OFF_K + r * STR + fc) * 4, kgbase + (size_t)r * Dd + fc);
        }
        CP_COMMIT();
#pragma unroll
        for (int i = 0; i < 4; i++) {
            int r = i * 16 + fr;
            cpa16(sbase + (uint32_t)(OFF_V + r * STR + fc) * 4, vgbase + (size_t)r * Dd + fc);
        }
        CP_COMMIT();
    }
    CP_WAIT1();          // Q + K0 complete; V0 may be in flight
    __syncthreads();

    float oacc[8][4];
#pragma unroll
    for (int n = 0; n < 8; n++)
#pragma unroll
        for (int i = 0; i < 4; i++) oacc[n][i] = 0.f;
    float lacc[2] = {0.f, 0.f};

    float* Pw = sm + OFF_P + wid * 16 * STR;
    const float* Ks = sm + OFF_K;
    const float* Vs = sm + OFF_V;

#pragma unroll 1
    for (int t64 = 0; t64 < 32; t64++) {
        const int k0 = t64 * 64;

        // ---- S = Q(16x64) @ K^T(64x64) per warp: 64 mma ----
        float sacc[8][4];
#pragma unroll
        for (int n = 0; n < 8; n++)
#pragma unroll
            for (int i = 0; i < 4; i++) sacc[n][i] = 0.f;

#pragma unroll
        for (int kk = 0; kk < 8; kk++) {
            uint32_t a[4];
            {
                const float* qrow = sm + OFF_Q + (wid * 16 + g) * STR + 8 * kk + q;
                a[0] = __float_as_uint(qrow[0]);
                a[1] = __float_as_uint(qrow[8 * STR]);
                a[2] = __float_as_uint(qrow[4]);
                a[3] = __float_as_uint(qrow[8 * STR + 4]);
            }
            uint32_t bf[8][2];
#pragma unroll
            for (int n = 0; n < 8; n++) {
                const float* krow = Ks + (8 * n + g) * STR + 8 * kk + q;
                bf[n][0] = __float_as_uint(krow[0]);
                bf[n][1] = __float_as_uint(krow[4]);
            }
#pragma unroll
            for (int n = 0; n < 8; n++)
                mma_tf32(sacc[n], a, bf[n]);
        }

        __syncthreads();   // all warps done reading K[t]
        if (t64 + 1 < 32) {
            const float* kg = kgbase + (size_t)(k0 + 64) * Dd;
#pragma unroll
            for (int i = 0; i < 4; i++) {
                int r = i * 16 + fr;
                cpa16(sbase + (uint32_t)(OFF_K + r * STR + fc) * 4, kg + (size_t)r * Dd + fc);
            }
            CP_COMMIT();   // outstanding: V[t], K[t+1]
        }

        // ---- softmax: P = maskbit * exp2(S*sc); row sums; store P ----
        {
            uint2 w0 = *(const uint2*)(mrow0 + (k0 >> 5));   // keys [k0, k0+64)
            uint2 w1 = *(const uint2*)(mrow1 + (k0 >> 5));
            float l0 = 0.f, l1 = 0.f;
#pragma unroll
            for (int n = 0; n < 8; n++) {
                const uint32_t u0 = (n < 4) ? w0.x : w0.y;
                const uint32_t u1 = (n < 4) ? w1.x : w1.y;
                const int j = 8 * (n & 3) + 2 * q;
                float p0 = ((u0 >> j) & 1u)       ? ex2(sacc[n][0] * SC_LOG2E) : 0.f;
                float p1 = ((u0 >> (j + 1)) & 1u) ? ex2(sacc[n][1] * SC_LOG2E) : 0.f;
                float p2 = ((u1 >> j) & 1u)       ? ex2(sacc[n][2] * SC_LOG2E) : 0.f;
                float p3 = ((u1 >> (j + 1)) & 1u) ? ex2(sacc[n][3] * SC_LOG2E) : 0.f;
                l0 += p0 + p1; l1 += p2 + p3;
                float2 s0; s0.x = tf32r(p0); s0.y = tf32r(p1);
                float2 s1; s1.x = tf32r(p2); s1.y = tf32r(p3);
                *(float2*)(Pw + g * STR + 8 * n + 2 * q) = s0;
                *(float2*)(Pw + (g + 8) * STR + 8 * n + 2 * q) = s1;
            }
            lacc[0] += l0;
            lacc[1] += l1;
        }

        if (t64 + 1 < 32) CP_WAIT1();   // V[t] (oldest) complete
        else              CP_WAIT0();
        __syncthreads();                // V[t] visible

        // ---- O += P(16x64) @ V(64x64): 64 mma ----
#pragma unroll
        for (int kk = 0; kk < 8; kk++) {
            uint32_t a[4];
            {
                const float* prow = Pw + g * STR + 8 * kk + q;
                a[0] = __float_as_uint(prow[0]);
                a[1] = __float_as_uint(prow[8 * STR]);
                a[2] = __float_as_uint(prow[4]);
                a[3] = __float_as_uint(prow[8 * STR + 4]);
            }
            uint32_t bf[8][2];
#pragma unroll
            for (int n = 0; n < 8; n++) {
                const float* vrow = Vs + (8 * kk + q) * STR + 8 * n + g;
                bf[n][0] = __float_as_uint(vrow[0]);
                bf[n][1] = __float_as_uint(vrow[4 * STR]);
            }
#pragma unroll
            for (int n = 0; n < 8; n++)
                mma_tf32(oacc[n], a, bf[n]);
        }

        if (t64 + 1 < 32) {
            __syncthreads();   // all warps done reading V[t]
            const float* vg = vgbase + (size_t)(k0 + 64) * Dd;
#pragma unroll
            for (int i = 0; i < 4; i++) {
                int r = i * 16 + fr;
                cpa16(sbase + (uint32_t)(OFF_V + r * STR + fc) * 4, vg + (size_t)r * Dd + fc);
            }
            CP_COMMIT();       // outstanding: K[t+1], V[t+1]
            CP_WAIT1();        // K[t+1] complete
            __syncthreads();   // K[t+1] visible
        }
    }

    // ---- reduce row sums across the quad ----
#pragma unroll
    for (int i = 0; i < 2; i++) {
        lacc[i] += __shfl_xor_sync(FULL, lacc[i], 1);
        lacc[i] += __shfl_xor_sync(FULL, lacc[i], 2);
    }
    const float inv0 = 1.f / lacc[0];
    const float inv1 = 1.f / lacc[1];

    // ---- write O ----
    float* og = O + ((size_t)(b * Nn + q0 + wid * 16)) * Dd + h * HD;
#pragma unroll
    for (int n = 0; n < 8; n++) {
        float2 w0;
        w0.x = oacc[n][0] * inv0;
        w0.y = oacc[n][1] * inv0;
        *(float2*)(og + (size_t)g * Dd + 8 * n + 2 * q) = w0;
        float2 w1;
        w1.x = oacc[n][2] * inv1;
        w1.y = oacc[n][3] * inv1;
        *(float2*)(og + (size_t)(g + 8) * Dd + 8 * n + 2 * q) = w1;
    }
}

// ================= LayerNorm (unchanged) =================
__global__ __launch_bounds__(128) void ln_kernel(
    const float* __restrict__ Y, const float* __restrict__ gamma,
    const float* __restrict__ beta, float* __restrict__ out)
{
    __shared__ float sbuf[4];
    __shared__ float smu, srstd;
    const int tid = threadIdx.x;
    const int row = blockIdx.x;
    const float* y = Y + (size_t)row * Dd;

    float4 v = ((const float4*)y)[tid];
    float sum = v.x + v.y + v.z + v.w;
    int lane = tid & 31, wid = tid >> 5;
#pragma unroll
    for (int off = 16; off > 0; off >>= 1) sum += __shfl_xor_sync(0xffffffffu, sum, off);
    if (lane == 0) sbuf[wid] = sum;
    __syncthreads();
    if (tid == 0) smu = (sbuf[0] + sbuf[1] + sbuf[2] + sbuf[3]) * (1.f / Dd);
    __syncthreads();
    float mu = smu;

    float dx = v.x - mu, dy = v.y - mu, dz = v.z - mu, dw = v.w - mu;
    float sq = dx * dx + dy * dy + dz * dz + dw * dw;
#pragma unroll
    for (int off = 16; off > 0; off >>= 1) sq += __shfl_xor_sync(0xffffffffu, sq, off);
    __syncthreads();
    if (lane == 0) sbuf[wid] = sq;
    __syncthreads();
    if (tid == 0) {
        float var = (sbuf[0] + sbuf[1] + sbuf[2] + sbuf[3]) * (1.f / Dd);
        srstd = rsqrtf(var + 1e-5f);
    }
    __syncthreads();
    float rstd = srstd;

    int c = tid * 4;
    float4 g = *(const float4*)(gamma + c);
    float4 be = *(const float4*)(beta + c);
    float4 r;
    r.x = dx * rstd * g.x + be.x;
    r.y = dy * rstd * g.y + be.y;
    r.z = dz * rstd * g.z + be.z;
    r.w = dw * rstd * g.w + be.w;
    ((float4*)(out + (size_t)row * Dd))[tid] = r;
}

// ================= launch =================
extern "C" void kernel_launch(void* const* d_in, const int* in_sizes, int n_in,
                              void* d_out, int out_size)
{
    const float* x     = (const float*)d_in[0];
    const int*   adj   = (const int*)d_in[1];
    const float* Wq    = (const float*)d_in[2];
    const float* bq    = (const float*)d_in[3];
    const float* Wk    = (const float*)d_in[4];
    const float* bk    = (const float*)d_in[5];
    const float* Wv    = (const float*)d_in[6];
    const float* bv    = (const float*)d_in[7];
    const float* Wo    = (const float*)d_in[8];
    const float* bo    = (const float*)d_in[9];
    const float* gamma = (const float*)d_in[10];
    const float* beta  = (const float*)d_in[11];
    float* out = (float*)d_out;

    float *Qb, *Kb, *Vb, *Hb, *Yb;
    uint32_t* Mbp;
    cudaGetSymbolAddress((void**)&Qb, g_Q);
    cudaGetSymbolAddress((void**)&Kb, g_K);
    cudaGetSymbolAddress((void**)&Vb, g_V);
    cudaGetSymbolAddress((void**)&Hb, g_Hh);
    cudaGetSymbolAddress((void**)&Yb, g_Y);
    cudaGetSymbolAddress((void**)&Mbp, g_Mb);

    cudaFuncSetAttribute(attn_mma_kernel, cudaFuncAttributeMaxDynamicSharedMemorySize, ATTN_SMEM_BYTES);

    pack_mask_kernel<<<(Mm * NW) / 256, 256>>>(adj, Mbp);

    dim3 ggrid(Dd / GBN, Mm / GBM);   // (8, 64)
    gemm_mma_kernel<<<ggrid, 256>>>(x, Wq, bq, nullptr, Qb, Mm, Dd, Dd, 1);
    gemm_mma_kernel<<<ggrid, 256>>>(x, Wk, bk, nullptr, Kb, Mm, Dd, Dd, 1);
    gemm_mma_kernel<<<ggrid, 256>>>(x, Wv, bv, nullptr, Vb, Mm, Dd, Dd, 1);

    dim3 agrid(Nn / 128, Hh, Bb);     // (16, 8, 4)
    attn_mma_kernel<<<agrid, 256, ATTN_SMEM_BYTES>>>(Qb, Kb, Vb, Mbp, Hb);

    gemm_mma_kernel<<<ggrid, 256>>>(Hb, Wo, bo, x, Yb, Mm, Dd, Dd, 0);

    ln_kernel<<<Mm, 128>>>(Yb, gamma, beta, out);
}

// round 14
// speedup vs baseline: 1.1981x; 1.0408x over previous
#include <cuda_runtime.h>
#include <cstdint>
#include <math.h>

#define Bb 4
#define Nn 2048
#define Dd 512
#define Hh 8
#define HD 64
#define Mm (Bb * Nn)   // 8192
#define NW (Nn / 32)   // 64 mask words per row
#define SC_LOG2E 0.18033688f   // 0.125 * log2(e)

// ---------------- scratch ----------------
__device__ float g_Q[(size_t)Mm * Dd];
__device__ float g_K[(size_t)Mm * Dd];
__device__ float g_V[(size_t)Mm * Dd];
__device__ float g_Hh[(size_t)Mm * Dd];
__device__ float g_Y[(size_t)Mm * Dd];
__device__ float g_Xr[(size_t)Mm * Dd];        // tf32-rounded x
__device__ float g_Wr[4][(size_t)Dd * Dd];     // tf32-rounded Wq,Wk,Wv,Wo
__device__ uint32_t g_Mb[(size_t)Mm * NW];     // bit-packed adjacency

// ---------------- helpers ----------------
__device__ __forceinline__ uint32_t smem_u32(const void* p) {
    uint32_t a;
    asm("{ .reg .u64 t; cvta.to.shared.u64 t, %1; cvt.u32.u64 %0, t; }" : "=r"(a) : "l"(p));
    return a;
}
__device__ __forceinline__ float ex2(float x) {
    float y; asm("ex2.approx.f32 %0, %1;" : "=f"(y) : "f"(x)); return y;
}
__device__ __forceinline__ float tf32r(float f) {
    uint32_t u; asm("cvt.rna.tf32.f32 %0, %1;" : "=r"(u) : "f"(f));
    return __uint_as_float(u);
}
__device__ __forceinline__ void mma_tf32(float* c, const uint32_t* a, const uint32_t* b) {
    asm volatile("mma.sync.aligned.m16n8k8.row.col.f32.tf32.tf32.f32 "
        "{%0,%1,%2,%3}, {%4,%5,%6,%7}, {%8,%9}, {%0,%1,%2,%3};"
        : "+f"(c[0]), "+f"(c[1]), "+f"(c[2]), "+f"(c[3])
        : "r"(a[0]), "r"(a[1]), "r"(a[2]), "r"(a[3]), "r"(b[0]), "r"(b[1]));
}
__device__ __forceinline__ void cpa16(uint32_t dst, const void* src) {
    asm volatile("cp.async.cg.shared.global [%0], [%1], 16;" :: "r"(dst), "l"(src));
}
#define CP_COMMIT() asm volatile("cp.async.commit_group;" ::: "memory")
#define CP_WAIT1()  asm volatile("cp.async.wait_group 1;" ::: "memory")
#define CP_WAIT0()  asm volatile("cp.async.wait_group 0;" ::: "memory")

// ---------------- pre-round kernel (fp32 -> tf32 RNA) ----------------
__global__ void __launch_bounds__(256) round_kernel(
    const float* __restrict__ in, float* __restrict__ out)
{
    int i = blockIdx.x * 256 + threadIdx.x;
    float4 v = ((const float4*)in)[i];
    v.x = tf32r(v.x); v.y = tf32r(v.y); v.z = tf32r(v.z); v.w = tf32r(v.w);
    ((float4*)out)[i] = v;
}

// ---------------- mask bit-pack ----------------
__global__ void __launch_bounds__(256) pack_mask_kernel(
    const int* __restrict__ adj, uint32_t* __restrict__ mb)
{
    int idx = blockIdx.x * 256 + threadIdx.x;   // word index
    const int4* src = (const int4*)(adj + (size_t)idx * 32);
    uint32_t w = 0;
#pragma unroll
    for (int i = 0; i < 8; i++) {
        int4 v = src[i];
        w |= (v.x != 0 ? 1u : 0u) << (4 * i + 0);
        w |= (v.y != 0 ? 1u : 0u) << (4 * i + 1);
        w |= (v.z != 0 ? 1u : 0u) << (4 * i + 2);
        w |= (v.w != 0 ? 1u : 0u) << (4 * i + 3);
    }
    mb[idx] = w;
}

// ======================================================================
// tf32 mma GEMM, cp.async double-buffered. Inputs MUST be pre-rounded.
// BM=128, BN=64, BK=32, 256 threads (8 warps 4x2), warp tile 32x32.
// ======================================================================
#define GBM 128
#define GBN 64
#define GBK 32
#define ASTR 36
#define BSTR 68
#define GSM_BUF (GBM * ASTR + GBK * BSTR)   // 6784 floats per buffer
#define GEMM_SMEM_BYTES (2 * GSM_BUF * 4)   // 54272

__global__ void __launch_bounds__(256, 3) gemm_mma_kernel(
    const float* __restrict__ A, const float* __restrict__ W,
    const float* __restrict__ bias, const float* __restrict__ resid,
    float* __restrict__ C, int M, int N, int K, int roundOut)
{
    extern __shared__ __align__(16) float gsm[];
    const uint32_t sbase = smem_u32(gsm);

    const int tid = threadIdx.x;
    const int wid = tid >> 5, lane = tid & 31;
    const int g = lane >> 2, q = lane & 3;
    const int wm = wid & 3, wn = wid >> 2;
    const int m0 = blockIdx.y * GBM;
    const int n0 = blockIdx.x * GBN;
    const int nk = K / GBK;

    const int ar0 = tid >> 3, ac0 = (tid & 7) * 4;   // 32 rows / pass
    const int wr0 = tid >> 4, wc0 = (tid & 15) * 4;  // 16 rows / pass

    auto issue = [&](int kt, int buf) {
        const float* Ab = A + (size_t)m0 * K + kt * GBK;
        const uint32_t as = sbase + (uint32_t)(buf * GSM_BUF) * 4;
        const uint32_t ws = as + (uint32_t)(GBM * ASTR) * 4;
#pragma unroll
        for (int i = 0; i < 4; i++) {
            int r = i * 32 + ar0;
            cpa16(as + (uint32_t)(r * ASTR + ac0) * 4, Ab + (size_t)r * K + ac0);
        }
#pragma unroll
        for (int i = 0; i < 2; i++) {
            int r = i * 16 + wr0;
            cpa16(ws + (uint32_t)(r * BSTR + wc0) * 4, W + (size_t)(kt * GBK + r) * N + n0 + wc0);
        }
        CP_COMMIT();
    };

    float acc[2][4][4];
#pragma unroll
    for (int t = 0; t < 2; t++)
#pragma unroll
        for (int nb = 0; nb < 4; nb++)
#pragma unroll
            for (int i = 0; i < 4; i++) acc[t][nb][i] = 0.f;

    issue(0, 0);

#pragma unroll 1
    for (int kt = 0; kt < nk; kt++) {
        const int buf = kt & 1;
        if (kt + 1 < nk) { issue(kt + 1, buf ^ 1); CP_WAIT1(); }
        else             { CP_WAIT0(); }
        __syncthreads();

        const float* As = gsm + buf * GSM_BUF;
        const float* Ws = As + GBM * ASTR;

#pragma unroll
        for (int kk = 0; kk < 4; kk++) {
            uint32_t a[2][4];
#pragma unroll
            for (int t = 0; t < 2; t++) {
                const float* arp = As + (wm * 32 + 16 * t + g) * ASTR + 8 * kk + q;
                a[t][0] = __float_as_uint(arp[0]);
                a[t][1] = __float_as_uint(arp[8 * ASTR]);
                a[t][2] = __float_as_uint(arp[4]);
                a[t][3] = __float_as_uint(arp[8 * ASTR + 4]);
            }
            uint32_t bf[4][2];
#pragma unroll
            for (int nb = 0; nb < 4; nb++) {
                const float* brp = Ws + (8 * kk + q) * BSTR + wn * 32 + 8 * nb + g;
                bf[nb][0] = __float_as_uint(brp[0]);
                bf[nb][1] = __float_as_uint(brp[4 * BSTR]);
            }
#pragma unroll
            for (int t = 0; t < 2; t++)
#pragma unroll
                for (int nb = 0; nb < 4; nb++)
                    mma_tf32(acc[t][nb], a[t], bf[nb]);
        }
        __syncthreads();   // all warps done with buf before it is refilled
    }

#pragma unroll
    for (int t = 0; t < 2; t++) {
        const int r0 = m0 + wm * 32 + 16 * t + g;
#pragma unroll
        for (int nb = 0; nb < 4; nb++) {
            const int c = n0 + wn * 32 + 8 * nb + 2 * q;
            float bx = bias[c], by = bias[c + 1];
            float2 w0, w1;
            w0.x = acc[t][nb][0] + bx; w0.y = acc[t][nb][1] + by;
            w1.x = acc[t][nb][2] + bx; w1.y = acc[t][nb][3] + by;
            if (resid) {
                float2 r4 = *(const float2*)(resid + (size_t)r0 * N + c);
                float2 r5 = *(const float2*)(resid + (size_t)(r0 + 8) * N + c);
                w0.x += r4.x; w0.y += r4.y;
                w1.x += r5.x; w1.y += r5.y;
            }
            if (roundOut) {
                w0.x = tf32r(w0.x); w0.y = tf32r(w0.y);
                w1.x = tf32r(w1.x); w1.y = tf32r(w1.y);
            }
            *(float2*)(C + (size_t)r0 * N + c) = w0;
            *(float2*)(C + (size_t)(r0 + 8) * N + c) = w1;
        }
    }
}

// ======================================================================
// mma.sync tf32 attention (R12 measured-best; H written tf32-rounded)
// 128 queries/CTA, 256 threads (8 warps), 16 queries/warp, 2 CTAs/SM.
// ======================================================================
#define STR 68
#define OFF_Q 0
#define OFF_K (128 * STR)
#define OFF_V (192 * STR)
#define OFF_P (256 * STR)
#define ATTN_SMEM_FLOATS (384 * STR)            // 26112
#define ATTN_SMEM_BYTES (ATTN_SMEM_FLOATS * 4)  // 104448

__global__ void __launch_bounds__(256, 2) attn_mma_kernel(
    const float* __restrict__ Q, const float* __restrict__ K,
    const float* __restrict__ V, const uint32_t* __restrict__ mb,
    float* __restrict__ O)
{
    extern __shared__ __align__(16) float sm[];
    const uint32_t sbase = smem_u32(sm);
    const int tid = threadIdx.x;
    const int wid = tid >> 5, lane = tid & 31;
    const int g = lane >> 2, q = lane & 3;
    const int h = blockIdx.y, b = blockIdx.z;
    const int q0 = blockIdx.x * 128;
    const unsigned FULL = 0xffffffffu;

    const int fr = tid >> 4, fc = (tid & 15) * 4;   // 16 rows per 256-thread pass

    const float* kgbase = K + ((size_t)(b * Nn)) * Dd + h * HD;
    const float* vgbase = V + ((size_t)(b * Nn)) * Dd + h * HD;
    const uint32_t* mrow0 = mb + (size_t)(b * Nn + q0 + wid * 16 + g) * NW;
    const uint32_t* mrow1 = mrow0 + (size_t)8 * NW;

    // ---- prologue: Q (group), K0 (group), V0 (group) via cp.async ----
    {
        const float* qg = Q + ((size_t)(b * Nn + q0)) * Dd + h * HD;
#pragma unroll
        for (int i = 0; i < 8; i++) {
            int r = i * 16 + fr;
            cpa16(sbase + (uint32_t)(OFF_Q + r * STR + fc) * 4, qg + (size_t)r * Dd + fc);
        }
        CP_COMMIT();
#pragma unroll
        for (int i = 0; i < 4; i++) {
            int r = i * 16 + fr;
            cpa16(sbase + (uint32_t)(OFF_K + r * STR + fc) * 4, kgbase + (size_t)r * Dd + fc);
        }
        CP_COMMIT();
#pragma unroll
        for (int i = 0; i < 4; i++) {
            int r = i * 16 + fr;
            cpa16(sbase + (uint32_t)(OFF_V + r * STR + fc) * 4, vgbase + (size_t)r * Dd + fc);
        }
        CP_COMMIT();
    }
    CP_WAIT1();          // Q + K0 complete; V0 may be in flight
    __syncthreads();

    float oacc[8][4];
#pragma unroll
    for (int n = 0; n < 8; n++)
#pragma unroll
        for (int i = 0; i < 4; i++) oacc[n][i] = 0.f;
    float lacc[2] = {0.f, 0.f};

    float* Pw = sm + OFF_P + wid * 16 * STR;
    const float* Ks = sm + OFF_K;
    const float* Vs = sm + OFF_V;

#pragma unroll 1
    for (int t64 = 0; t64 < 32; t64++) {
        const int k0 = t64 * 64;

        // ---- S = Q(16x64) @ K^T(64x64) per warp: 64 mma ----
        float sacc[8][4];
#pragma unroll
        for (int n = 0; n < 8; n++)
#pragma unroll
            for (int i = 0; i < 4; i++) sacc[n][i] = 0.f;

#pragma unroll
        for (int kk = 0; kk < 8; kk++) {
            uint32_t a[4];
            {
                const float* qrow = sm + OFF_Q + (wid * 16 + g) * STR + 8 * kk + q;
                a[0] = __float_as_uint(qrow[0]);
                a[1] = __float_as_uint(qrow[8 * STR]);
                a[2] = __float_as_uint(qrow[4]);
                a[3] = __float_as_uint(qrow[8 * STR + 4]);
            }
            uint32_t bf[8][2];
#pragma unroll
            for (int n = 0; n < 8; n++) {
                const float* krow = Ks + (8 * n + g) * STR + 8 * kk + q;
                bf[n][0] = __float_as_uint(krow[0]);
                bf[n][1] = __float_as_uint(krow[4]);
            }
#pragma unroll
            for (int n = 0; n < 8; n++)
                mma_tf32(sacc[n], a, bf[n]);
        }

        __syncthreads();   // all warps done reading K[t]
        if (t64 + 1 < 32) {
            const float* kg = kgbase + (size_t)(k0 + 64) * Dd;
#pragma unroll
            for (int i = 0; i < 4; i++) {
                int r = i * 16 + fr;
                cpa16(sbase + (uint32_t)(OFF_K + r * STR + fc) * 4, kg + (size_t)r * Dd + fc);
            }
            CP_COMMIT();   // outstanding: V[t], K[t+1]
        }

        // ---- softmax: P = maskbit * exp2(S*sc); row sums; store P ----
        {
            uint2 w0 = *(const uint2*)(mrow0 + (k0 >> 5));   // keys [k0, k0+64)
            uint2 w1 = *(const uint2*)(mrow1 + (k0 >> 5));
            float l0 = 0.f, l1 = 0.f;
#pragma unroll
            for (int n = 0; n < 8; n++) {
                const uint32_t u0 = (n < 4) ? w0.x : w0.y;
                const uint32_t u1 = (n < 4) ? w1.x : w1.y;
                const int j = 8 * (n & 3) + 2 * q;
                float p0 = ((u0 >> j) & 1u)       ? ex2(sacc[n][0] * SC_LOG2E) : 0.f;
                float p1 = ((u0 >> (j + 1)) & 1u) ? ex2(sacc[n][1] * SC_LOG2E) : 0.f;
                float p2 = ((u1 >> j) & 1u)       ? ex2(sacc[n][2] * SC_LOG2E) : 0.f;
                float p3 = ((u1 >> (j + 1)) & 1u) ? ex2(sacc[n][3] * SC_LOG2E) : 0.f;
                l0 += p0 + p1; l1 += p2 + p3;
                float2 s0; s0.x = tf32r(p0); s0.y = tf32r(p1);
                float2 s1; s1.x = tf32r(p2); s1.y = tf32r(p3);
                *(float2*)(Pw + g * STR + 8 * n + 2 * q) = s0;
                *(float2*)(Pw + (g + 8) * STR + 8 * n + 2 * q) = s1;
            }
            lacc[0] += l0;
            lacc[1] += l1;
        }

        if (t64 + 1 < 32) CP_WAIT1();   // V[t] (oldest) complete
        else              CP_WAIT0();
        __syncthreads();                // V[t] visible

        // ---- O += P(16x64) @ V(64x64): 64 mma ----
#pragma unroll
        for (int kk = 0; kk < 8; kk++) {
            uint32_t a[4];
            {
                const float* prow = Pw + g * STR + 8 * kk + q;
                a[0] = __float_as_uint(prow[0]);
                a[1] = __float_as_uint(prow[8 * STR]);
                a[2] = __float_as_uint(prow[4]);
                a[3] = __float_as_uint(prow[8 * STR + 4]);
            }
            uint32_t bf[8][2];
#pragma unroll
            for (int n = 0; n < 8; n++) {
                const float* vrow = Vs + (8 * kk + q) * STR + 8 * n + g;
                bf[n][0] = __float_as_uint(vrow[0]);
                bf[n][1] = __float_as_uint(vrow[4 * STR]);
            }
#pragma unroll
            for (int n = 0; n < 8; n++)
                mma_tf32(oacc[n], a, bf[n]);
        }

        if (t64 + 1 < 32) {
            __syncthreads();   // all warps done reading V[t]
            const float* vg = vgbase + (size_t)(k0 + 64) * Dd;
#pragma unroll
            for (int i = 0; i < 4; i++) {
                int r = i * 16 + fr;
                cpa16(sbase + (uint32_t)(OFF_V + r * STR + fc) * 4, vg + (size_t)r * Dd + fc);
            }
            CP_COMMIT();       // outstanding: K[t+1], V[t+1]
            CP_WAIT1();        // K[t+1] complete
            __syncthreads();   // K[t+1] visible
        }
    }

    // ---- reduce row sums across the quad ----
#pragma unroll
    for (int i = 0; i < 2; i++) {
        lacc[i] += __shfl_xor_sync(FULL, lacc[i], 1);
        lacc[i] += __shfl_xor_sync(FULL, lacc[i], 2);
    }
    const float inv0 = 1.f / lacc[0];
    const float inv1 = 1.f / lacc[1];

    // ---- write H (tf32-rounded: consumed by cp.async Wo GEMM) ----
    float* og = O + ((size_t)(b * Nn + q0 + wid * 16)) * Dd + h * HD;
#pragma unroll
    for (int n = 0; n < 8; n++) {
        float2 w0;
        w0.x = tf32r(oacc[n][0] * inv0);
        w0.y = tf32r(oacc[n][1] * inv0);
        *(float2*)(og + (size_t)g * Dd + 8 * n + 2 * q) = w0;
        float2 w1;
        w1.x = tf32r(oacc[n][2] * inv1);
        w1.y = tf32r(oacc[n][3] * inv1);
        *(float2*)(og + (size_t)(g + 8) * Dd + 8 * n + 2 * q) = w1;
    }
}

// ================= LayerNorm (unchanged) =================
__global__ __launch_bounds__(128) void ln_kernel(
    const float* __restrict__ Y, const float* __restrict__ gamma,
    const float* __restrict__ beta, float* __restrict__ out)
{
    __shared__ float sbuf[4];
    __shared__ float smu, srstd;
    const int tid = threadIdx.x;
    const int row = blockIdx.x;
    const float* y = Y + (size_t)row * Dd;

    float4 v = ((const float4*)y)[tid];
    float sum = v.x + v.y + v.z + v.w;
    int lane = tid & 31, wid = tid >> 5;
#pragma unroll
    for (int off = 16; off > 0; off >>= 1) sum += __shfl_xor_sync(0xffffffffu, sum, off);
    if (lane == 0) sbuf[wid] = sum;
    __syncthreads();
    if (tid == 0) smu = (sbuf[0] + sbuf[1] + sbuf[2] + sbuf[3]) * (1.f / Dd);
    __syncthreads();
    float mu = smu;

    float dx = v.x - mu, dy = v.y - mu, dz = v.z - mu, dw = v.w - mu;
    float sq = dx * dx + dy * dy + dz * dz + dw * dw;
#pragma unroll
    for (int off = 16; off > 0; off >>= 1) sq += __shfl_xor_sync(0xffffffffu, sq, off);
    __syncthreads();
    if (lane == 0) sbuf[wid] = sq;
    __syncthreads();
    if (tid == 0) {
        float var = (sbuf[0] + sbuf[1] + sbuf[2] + sbuf[3]) * (1.f / Dd);
        srstd = rsqrtf(var + 1e-5f);
    }
    __syncthreads();
    float rstd = srstd;

    int c = tid * 4;
    float4 g = *(const float4*)(gamma + c);
    float4 be = *(const float4*)(beta + c);
    float4 r;
    r.x = dx * rstd * g.x + be.x;
    r.y = dy * rstd * g.y + be.y;
    r.z = dz * rstd * g.z + be.z;
    r.w = dw * rstd * g.w + be.w;
    ((float4*)(out + (size_t)row * Dd))[tid] = r;
}

// ================= launch =================
extern "C" void kernel_launch(void* const* d_in, const int* in_sizes, int n_in,
                              void* d_out, int out_size)
{
    const float* x     = (const float*)d_in[0];
    const int*   adj   = (const int*)d_in[1];
    const float* Wq    = (const float*)d_in[2];
    const float* bq    = (const float*)d_in[3];
    const float* Wk    = (const float*)d_in[4];
    const float* bk    = (const float*)d_in[5];
    const float* Wv    = (const float*)d_in[6];
    const float* bv    = (const float*)d_in[7];
    const float* Wo    = (const float*)d_in[8];
    const float* bo    = (const float*)d_in[9];
    const float* gamma = (const float*)d_in[10];
    const float* beta  = (const float*)d_in[11];
    float* out = (float*)d_out;

    float *Qb, *Kb, *Vb, *Hb, *Yb, *Xr, *Wr;
    uint32_t* Mbp;
    cudaGetSymbolAddress((void**)&Qb, g_Q);
    cudaGetSymbolAddress((void**)&Kb, g_K);
    cudaGetSymbolAddress((void**)&Vb, g_V);
    cudaGetSymbolAddress((void**)&Hb, g_Hh);
    cudaGetSymbolAddress((void**)&Yb, g_Y);
    cudaGetSymbolAddress((void**)&Xr, g_Xr);
    cudaGetSymbolAddress((void**)&Wr, g_Wr);
    cudaGetSymbolAddress((void**)&Mbp, g_Mb);
    float* Wr0 = Wr;
    float* Wr1 = Wr + (size_t)Dd * Dd;
    float* Wr2 = Wr + (size_t)2 * Dd * Dd;
    float* Wr3 = Wr + (size_t)3 * Dd * Dd;

    cudaFuncSetAttribute(attn_mma_kernel, cudaFuncAttributeMaxDynamicSharedMemorySize, ATTN_SMEM_BYTES);
    cudaFuncSetAttribute(gemm_mma_kernel, cudaFuncAttributeMaxDynamicSharedMemorySize, GEMM_SMEM_BYTES);

    pack_mask_kernel<<<(Mm * NW) / 256, 256>>>(adj, Mbp);
    round_kernel<<<(Mm * Dd / 4) / 256, 256>>>(x, Xr);
    round_kernel<<<(Dd * Dd / 4) / 256, 256>>>(Wq, Wr0);
    round_kernel<<<(Dd * Dd / 4) / 256, 256>>>(Wk, Wr1);
    round_kernel<<<(Dd * Dd / 4) / 256, 256>>>(Wv, Wr2);
    round_kernel<<<(Dd * Dd / 4) / 256, 256>>>(Wo, Wr3);

    dim3 ggrid(Dd / GBN, Mm / GBM);   // (8, 64)
    gemm_mma_kernel<<<ggrid, 256, GEMM_SMEM_BYTES>>>(Xr, Wr0, bq, nullptr, Qb, Mm, Dd, Dd, 1);
    gemm_mma_kernel<<<ggrid, 256, GEMM_SMEM_BYTES>>>(Xr, Wr1, bk, nullptr, Kb, Mm, Dd, Dd, 1);
    gemm_mma_kernel<<<ggrid, 256, GEMM_SMEM_BYTES>>>(Xr, Wr2, bv, nullptr, Vb, Mm, Dd, Dd, 1);

    dim3 agrid(Nn / 128, Hh, Bb);     // (16, 8, 4)
    attn_mma_kernel<<<agrid, 256, ATTN_SMEM_BYTES>>>(Qb, Kb, Vb, Mbp, Hb);

    gemm_mma_kernel<<<ggrid, 256, GEMM_SMEM_BYTES>>>(Hb, Wr3, bo, x, Yb, Mm, Dd, Dd, 0);

    ln_kernel<<<Mm, 128>>>(Yb, gamma, beta, out);
}

// round 15
// speedup vs baseline: 1.2412x; 1.0360x over previous
#include <cuda_runtime.h>
#include <cstdint>
#include <math.h>

#define Bb 4
#define Nn 2048
#define Dd 512
#define Hh 8
#define HD 64
#define Mm (Bb * Nn)   // 8192
#define NW (Nn / 32)   // 64 mask words per row
#define SC_LOG2E 0.18033688f   // 0.125 * log2(e)

// ---------------- scratch ----------------
__device__ float g_Q[(size_t)Mm * Dd];
__device__ float g_K[(size_t)Mm * Dd];
__device__ float g_V[(size_t)Mm * Dd];
__device__ float g_Hh[(size_t)Mm * Dd];
__device__ float g_Y[(size_t)Mm * Dd];
__device__ float g_Xr[(size_t)Mm * Dd];        // tf32-rounded x
__device__ float g_Wr[4][(size_t)Dd * Dd];     // tf32-rounded Wq,Wk,Wv,Wo
__device__ uint32_t g_Mb[(size_t)Mm * NW];     // bit-packed adjacency

// ---------------- helpers ----------------
__device__ __forceinline__ uint32_t smem_u32(const void* p) {
    uint32_t a;
    asm("{ .reg .u64 t; cvta.to.shared.u64 t, %1; cvt.u32.u64 %0, t; }" : "=r"(a) : "l"(p));
    return a;
}
__device__ __forceinline__ float ex2(float x) {
    float y; asm("ex2.approx.f32 %0, %1;" : "=f"(y) : "f"(x)); return y;
}
__device__ __forceinline__ float tf32r(float f) {
    uint32_t u; asm("cvt.rna.tf32.f32 %0, %1;" : "=r"(u) : "f"(f));
    return __uint_as_float(u);
}
__device__ __forceinline__ void mma_tf32(float* c, const uint32_t* a, const uint32_t* b) {
    asm volatile("mma.sync.aligned.m16n8k8.row.col.f32.tf32.tf32.f32 "
        "{%0,%1,%2,%3}, {%4,%5,%6,%7}, {%8,%9}, {%0,%1,%2,%3};"
        : "+f"(c[0]), "+f"(c[1]), "+f"(c[2]), "+f"(c[3])
        : "r"(a[0]), "r"(a[1]), "r"(a[2]), "r"(a[3]), "r"(b[0]), "r"(b[1]));
}
__device__ __forceinline__ void cpa16(uint32_t dst, const void* src) {
    asm volatile("cp.async.cg.shared.global [%0], [%1], 16;" :: "r"(dst), "l"(src));
}
#define CP_COMMIT() asm volatile("cp.async.commit_group;" ::: "memory")
#define CP_WAIT1()  asm volatile("cp.async.wait_group 1;" ::: "memory")
#define CP_WAIT0()  asm volatile("cp.async.wait_group 0;" ::: "memory")

// ---------------- pre-round kernel (fp32 -> tf32 RNA) ----------------
__global__ void __launch_bounds__(256) round_kernel(
    const float* __restrict__ in, float* __restrict__ out)
{
    int i = blockIdx.x * 256 + threadIdx.x;
    float4 v = ((const float4*)in)[i];
    v.x = tf32r(v.x); v.y = tf32r(v.y); v.z = tf32r(v.z); v.w = tf32r(v.w);
    ((float4*)out)[i] = v;
}

// ---------------- mask bit-pack ----------------
__global__ void __launch_bounds__(256) pack_mask_kernel(
    const int* __restrict__ adj, uint32_t* __restrict__ mb)
{
    int idx = blockIdx.x * 256 + threadIdx.x;   // word index
    const int4* src = (const int4*)(adj + (size_t)idx * 32);
    uint32_t w = 0;
#pragma unroll
    for (int i = 0; i < 8; i++) {
        int4 v = src[i];
        w |= (v.x != 0 ? 1u : 0u) << (4 * i + 0);
        w |= (v.y != 0 ? 1u : 0u) << (4 * i + 1);
        w |= (v.z != 0 ? 1u : 0u) << (4 * i + 2);
        w |= (v.w != 0 ? 1u : 0u) << (4 * i + 3);
    }
    mb[idx] = w;
}

// ======================================================================
// tf32 mma GEMM, cp.async double-buffered, BN widened to 128.
// BM=128, BN=128, BK=32, 256 threads (8 warps 4x2), warp tile 32x64.
// Inputs MUST be pre-rounded to tf32.
// ======================================================================
#define GBM 128
#define GBN 128
#define GBK 32
#define ASTR 36
#define BSTR 132
#define GSM_BUF (GBM * ASTR + GBK * BSTR)   // 8832 floats per buffer
#define GEMM_SMEM_BYTES (2 * GSM_BUF * 4)   // 70656

__global__ void __launch_bounds__(256, 2) gemm_mma_kernel(
    const float* __restrict__ A, const float* __restrict__ W,
    const float* __restrict__ bias, const float* __restrict__ resid,
    float* __restrict__ C, int M, int N, int K, int roundOut)
{
    extern __shared__ __align__(16) float gsm[];
    const uint32_t sbase = smem_u32(gsm);

    const int tid = threadIdx.x;
    const int wid = tid >> 5, lane = tid & 31;
    const int g = lane >> 2, q = lane & 3;
    const int wm = wid & 3, wn = wid >> 2;
    const int m0 = blockIdx.y * GBM;
    const int n0 = blockIdx.x * GBN;
    const int nk = K / GBK;

    const int ar0 = tid >> 3, ac0 = (tid & 7) * 4;    // A: 32 rows / pass
    const int wr0 = tid >> 5, wc0 = (tid & 31) * 4;   // W: 8 rows / pass

    auto issue = [&](int kt, int buf) {
        const float* Ab = A + (size_t)m0 * K + kt * GBK;
        const uint32_t as = sbase + (uint32_t)(buf * GSM_BUF) * 4;
        const uint32_t ws = as + (uint32_t)(GBM * ASTR) * 4;
#pragma unroll
        for (int i = 0; i < 4; i++) {
            int r = i * 32 + ar0;
            cpa16(as + (uint32_t)(r * ASTR + ac0) * 4, Ab + (size_t)r * K + ac0);
        }
#pragma unroll
        for (int i = 0; i < 4; i++) {
            int r = i * 8 + wr0;
            cpa16(ws + (uint32_t)(r * BSTR + wc0) * 4, W + (size_t)(kt * GBK + r) * N + n0 + wc0);
        }
        CP_COMMIT();
    };

    float acc[2][8][4];
#pragma unroll
    for (int t = 0; t < 2; t++)
#pragma unroll
        for (int nb = 0; nb < 8; nb++)
#pragma unroll
            for (int i = 0; i < 4; i++) acc[t][nb][i] = 0.f;

    issue(0, 0);

#pragma unroll 1
    for (int kt = 0; kt < nk; kt++) {
        const int buf = kt & 1;
        if (kt + 1 < nk) { issue(kt + 1, buf ^ 1); CP_WAIT1(); }
        else             { CP_WAIT0(); }
        __syncthreads();

        const float* As = gsm + buf * GSM_BUF;
        const float* Ws = As + GBM * ASTR;

#pragma unroll
        for (int kk = 0; kk < 4; kk++) {
            uint32_t a[2][4];
#pragma unroll
            for (int t = 0; t < 2; t++) {
                const float* arp = As + (wm * 32 + 16 * t + g) * ASTR + 8 * kk + q;
                a[t][0] = __float_as_uint(arp[0]);
                a[t][1] = __float_as_uint(arp[8 * ASTR]);
                a[t][2] = __float_as_uint(arp[4]);
                a[t][3] = __float_as_uint(arp[8 * ASTR + 4]);
            }
            uint32_t bf[8][2];
#pragma unroll
            for (int nb = 0; nb < 8; nb++) {
                const float* brp = Ws + (8 * kk + q) * BSTR + wn * 64 + 8 * nb + g;
                bf[nb][0] = __float_as_uint(brp[0]);
                bf[nb][1] = __float_as_uint(brp[4 * BSTR]);
            }
#pragma unroll
            for (int t = 0; t < 2; t++)
#pragma unroll
                for (int nb = 0; nb < 8; nb++)
                    mma_tf32(acc[t][nb], a[t], bf[nb]);
        }
        __syncthreads();   // all warps done with buf before it is refilled
    }

#pragma unroll
    for (int t = 0; t < 2; t++) {
        const int r0 = m0 + wm * 32 + 16 * t + g;
#pragma unroll
        for (int nb = 0; nb < 8; nb++) {
            const int c = n0 + wn * 64 + 8 * nb + 2 * q;
            float bx = bias[c], by = bias[c + 1];
            float2 w0, w1;
            w0.x = acc[t][nb][0] + bx; w0.y = acc[t][nb][1] + by;
            w1.x = acc[t][nb][2] + bx; w1.y = acc[t][nb][3] + by;
            if (resid) {
                float2 r4 = *(const float2*)(resid + (size_t)r0 * N + c);
                float2 r5 = *(const float2*)(resid + (size_t)(r0 + 8) * N + c);
                w0.x += r4.x; w0.y += r4.y;
                w1.x += r5.x; w1.y += r5.y;
            }
            if (roundOut) {
                w0.x = tf32r(w0.x); w0.y = tf32r(w0.y);
                w1.x = tf32r(w1.x); w1.y = tf32r(w1.y);
            }
            *(float2*)(C + (size_t)r0 * N + c) = w0;
            *(float2*)(C + (size_t)(r0 + 8) * N + c) = w1;
        }
    }
}

// ======================================================================
// mma.sync tf32 attention (R12/R14 measured-best; unchanged)
// 128 queries/CTA, 256 threads (8 warps), 16 queries/warp, 2 CTAs/SM.
// ======================================================================
#define STR 68
#define OFF_Q 0
#define OFF_K (128 * STR)
#define OFF_V (192 * STR)
#define OFF_P (256 * STR)
#define ATTN_SMEM_FLOATS (384 * STR)            // 26112
#define ATTN_SMEM_BYTES (ATTN_SMEM_FLOATS * 4)  // 104448

__global__ void __launch_bounds__(256, 2) attn_mma_kernel(
    const float* __restrict__ Q, const float* __restrict__ K,
    const float* __restrict__ V, const uint32_t* __restrict__ mb,
    float* __restrict__ O)
{
    extern __shared__ __align__(16) float sm[];
    const uint32_t sbase = smem_u32(sm);
    const int tid = threadIdx.x;
    const int wid = tid >> 5, lane = tid & 31;
    const int g = lane >> 2, q = lane & 3;
    const int h = blockIdx.y, b = blockIdx.z;
    const int q0 = blockIdx.x * 128;
    const unsigned FULL = 0xffffffffu;

    const int fr = tid >> 4, fc = (tid & 15) * 4;   // 16 rows per 256-thread pass

    const float* kgbase = K + ((size_t)(b * Nn)) * Dd + h * HD;
    const float* vgbase = V + ((size_t)(b * Nn)) * Dd + h * HD;
    const uint32_t* mrow0 = mb + (size_t)(b * Nn + q0 + wid * 16 + g) * NW;
    const uint32_t* mrow1 = mrow0 + (size_t)8 * NW;

    // ---- prologue: Q (group), K0 (group), V0 (group) via cp.async ----
    {
        const float* qg = Q + ((size_t)(b * Nn + q0)) * Dd + h * HD;
#pragma unroll
        for (int i = 0; i < 8; i++) {
            int r = i * 16 + fr;
            cpa16(sbase + (uint32_t)(OFF_Q + r * STR + fc) * 4, qg + (size_t)r * Dd + fc);
        }
        CP_COMMIT();
#pragma unroll
        for (int i = 0; i < 4; i++) {
            int r = i * 16 + fr;
            cpa16(sbase + (uint32_t)(OFF_K + r * STR + fc) * 4, kgbase + (size_t)r * Dd + fc);
        }
        CP_COMMIT();
#pragma unroll
        for (int i = 0; i < 4; i++) {
            int r = i * 16 + fr;
            cpa16(sbase + (uint32_t)(OFF_V + r * STR + fc) * 4, vgbase + (size_t)r * Dd + fc);
        }
        CP_COMMIT();
    }
    CP_WAIT1();          // Q + K0 complete; V0 may be in flight
    __syncthreads();

    float oacc[8][4];
#pragma unroll
    for (int n = 0; n < 8; n++)
#pragma unroll
        for (int i = 0; i < 4; i++) oacc[n][i] = 0.f;
    float lacc[2] = {0.f, 0.f};

    float* Pw = sm + OFF_P + wid * 16 * STR;
    const float* Ks = sm + OFF_K;
    const float* Vs = sm + OFF_V;

#pragma unroll 1
    for (int t64 = 0; t64 < 32; t64++) {
        const int k0 = t64 * 64;

        // ---- S = Q(16x64) @ K^T(64x64) per warp: 64 mma ----
        float sacc[8][4];
#pragma unroll
        for (int n = 0; n < 8; n++)
#pragma unroll
            for (int i = 0; i < 4; i++) sacc[n][i] = 0.f;

#pragma unroll
        for (int kk = 0; kk < 8; kk++) {
            uint32_t a[4];
            {
                const float* qrow = sm + OFF_Q + (wid * 16 + g) * STR + 8 * kk + q;
                a[0] = __float_as_uint(qrow[0]);
                a[1] = __float_as_uint(qrow[8 * STR]);
                a[2] = __float_as_uint(qrow[4]);
                a[3] = __float_as_uint(qrow[8 * STR + 4]);
            }
            uint32_t bf[8][2];
#pragma unroll
            for (int n = 0; n < 8; n++) {
                const float* krow = Ks + (8 * n + g) * STR + 8 * kk + q;
                bf[n][0] = __float_as_uint(krow[0]);
                bf[n][1] = __float_as_uint(krow[4]);
            }
#pragma unroll
            for (int n = 0; n < 8; n++)
                mma_tf32(sacc[n], a, bf[n]);
        }

        __syncthreads();   // all warps done reading K[t]
        if (t64 + 1 < 32) {
            const float* kg = kgbase + (size_t)(k0 + 64) * Dd;
#pragma unroll
            for (int i = 0; i < 4; i++) {
                int r = i * 16 + fr;
                cpa16(sbase + (uint32_t)(OFF_K + r * STR + fc) * 4, kg + (size_t)r * Dd + fc);
            }
            CP_COMMIT();   // outstanding: V[t], K[t+1]
        }

        // ---- softmax: P = maskbit * exp2(S*sc); row sums; store P ----
        {
            uint2 w0 = *(const uint2*)(mrow0 + (k0 >> 5));   // keys [k0, k0+64)
            uint2 w1 = *(const uint2*)(mrow1 + (k0 >> 5));
            float l0 = 0.f, l1 = 0.f;
#pragma unroll
            for (int n = 0; n < 8; n++) {
                const uint32_t u0 = (n < 4) ? w0.x : w0.y;
                const uint32_t u1 = (n < 4) ? w1.x : w1.y;
                const int j = 8 * (n & 3) + 2 * q;
                float p0 = ((u0 >> j) & 1u)       ? ex2(sacc[n][0] * SC_LOG2E) : 0.f;
                float p1 = ((u0 >> (j + 1)) & 1u) ? ex2(sacc[n][1] * SC_LOG2E) : 0.f;
                float p2 = ((u1 >> j) & 1u)       ? ex2(sacc[n][2] * SC_LOG2E) : 0.f;
                float p3 = ((u1 >> (j + 1)) & 1u) ? ex2(sacc[n][3] * SC_LOG2E) : 0.f;
                l0 += p0 + p1; l1 += p2 + p3;
                float2 s0; s0.x = tf32r(p0); s0.y = tf32r(p1);
                float2 s1; s1.x = tf32r(p2); s1.y = tf32r(p3);
                *(float2*)(Pw + g * STR + 8 * n + 2 * q) = s0;
                *(float2*)(Pw + (g + 8) * STR + 8 * n + 2 * q) = s1;
            }
            lacc[0] += l0;
            lacc[1] += l1;
        }

        if (t64 + 1 < 32) CP_WAIT1();   // V[t] (oldest) complete
        else              CP_WAIT0();
        __syncthreads();                // V[t] visible

        // ---- O += P(16x64) @ V(64x64): 64 mma ----
#pragma unroll
        for (int kk = 0; kk < 8; kk++) {
            uint32_t a[4];
            {
                const float* prow = Pw + g * STR + 8 * kk + q;
                a[0] = __float_as_uint(prow[0]);
                a[1] = __float_as_uint(prow[8 * STR]);
                a[2] = __float_as_uint(prow[4]);
                a[3] = __float_as_uint(prow[8 * STR + 4]);
            }
            uint32_t bf[8][2];
#pragma unroll
            for (int n = 0; n < 8; n++) {
                const float* vrow = Vs + (8 * kk + q) * STR + 8 * n + g;
                bf[n][0] = __float_as_uint(vrow[0]);
                bf[n][1] = __float_as_uint(vrow[4 * STR]);
            }
#pragma unroll
            for (int n = 0; n < 8; n++)
                mma_tf32(oacc[n], a, bf[n]);
        }

        if (t64 + 1 < 32) {
            __syncthreads();   // all warps done reading V[t]
            const float* vg = vgbase + (size_t)(k0 + 64) * Dd;
#pragma unroll
            for (int i = 0; i < 4; i++) {
                int r = i * 16 + fr;
                cpa16(sbase + (uint32_t)(OFF_V + r * STR + fc) * 4, vg + (size_t)r * Dd + fc);
            }
            CP_COMMIT();       // outstanding: K[t+1], V[t+1]
            CP_WAIT1();        // K[t+1] complete
            __syncthreads();   // K[t+1] visible
        }
    }

    // ---- reduce row sums across the quad ----
#pragma unroll
    for (int i = 0; i < 2; i++) {
        lacc[i] += __shfl_xor_sync(FULL, lacc[i], 1);
        lacc[i] += __shfl_xor_sync(FULL, lacc[i], 2);
    }
    const float inv0 = 1.f / lacc[0];
    const float inv1 = 1.f / lacc[1];

    // ---- write H (tf32-rounded: consumed by cp.async Wo GEMM) ----
    float* og = O + ((size_t)(b * Nn + q0 + wid * 16)) * Dd + h * HD;
#pragma unroll
    for (int n = 0; n < 8; n++) {
        float2 w0;
        w0.x = tf32r(oacc[n][0] * inv0);
        w0.y = tf32r(oacc[n][1] * inv0);
        *(float2*)(og + (size_t)g * Dd + 8 * n + 2 * q) = w0;
        float2 w1;
        w1.x = tf32r(oacc[n][2] * inv1);
        w1.y = tf32r(oacc[n][3] * inv1);
        *(float2*)(og + (size_t)(g + 8) * Dd + 8 * n + 2 * q) = w1;
    }
}

// ================= LayerNorm (unchanged) =================
__global__ __launch_bounds__(128) void ln_kernel(
    const float* __restrict__ Y, const float* __restrict__ gamma,
    const float* __restrict__ beta, float* __restrict__ out)
{
    __shared__ float sbuf[4];
    __shared__ float smu, srstd;
    const int tid = threadIdx.x;
    const int row = blockIdx.x;
    const float* y = Y + (size_t)row * Dd;

    float4 v = ((const float4*)y)[tid];
    float sum = v.x + v.y + v.z + v.w;
    int lane = tid & 31, wid = tid >> 5;
#pragma unroll
    for (int off = 16; off > 0; off >>= 1) sum += __shfl_xor_sync(0xffffffffu, sum, off);
    if (lane == 0) sbuf[wid] = sum;
    __syncthreads();
    if (tid == 0) smu = (sbuf[0] + sbuf[1] + sbuf[2] + sbuf[3]) * (1.f / Dd);
    __syncthreads();
    float mu = smu;

    float dx = v.x - mu, dy = v.y - mu, dz = v.z - mu, dw = v.w - mu;
    float sq = dx * dx + dy * dy + dz * dz + dw * dw;
#pragma unroll
    for (int off = 16; off > 0; off >>= 1) sq += __shfl_xor_sync(0xffffffffu, sq, off);
    __syncthreads();
    if (lane == 0) sbuf[wid] = sq;
    __syncthreads();
    if (tid == 0) {
        float var = (sbuf[0] + sbuf[1] + sbuf[2] + sbuf[3]) * (1.f / Dd);
        srstd = rsqrtf(var + 1e-5f);
    }
    __syncthreads();
    float rstd = srstd;

    int c = tid * 4;
    float4 g = *(const float4*)(gamma + c);
    float4 be = *(const float4*)(beta + c);
    float4 r;
    r.x = dx * rstd * g.x + be.x;
    r.y = dy * rstd * g.y + be.y;
    r.z = dz * rstd * g.z + be.z;
    r.w = dw * rstd * g.w + be.w;
    ((float4*)(out + (size_t)row * Dd))[tid] = r;
}

// ================= launch =================
extern "C" void kernel_launch(void* const* d_in, const int* in_sizes, int n_in,
                              void* d_out, int out_size)
{
    const float* x     = (const float*)d_in[0];
    const int*   adj   = (const int*)d_in[1];
    const float* Wq    = (const float*)d_in[2];
    const float* bq    = (const float*)d_in[3];
    const float* Wk    = (const float*)d_in[4];
    const float* bk    = (const float*)d_in[5];
    const float* Wv    = (const float*)d_in[6];
    const float* bv    = (const float*)d_in[7];
    const float* Wo    = (const float*)d_in[8];
    const float* bo    = (const float*)d_in[9];
    const float* gamma = (const float*)d_in[10];
    const float* beta  = (const float*)d_in[11];
    float* out = (float*)d_out;

    float *Qb, *Kb, *Vb, *Hb, *Yb, *Xr, *Wr;
    uint32_t* Mbp;
    cudaGetSymbolAddress((void**)&Qb, g_Q);
    cudaGetSymbolAddress((void**)&Kb, g_K);
    cudaGetSymbolAddress((void**)&Vb, g_V);
    cudaGetSymbolAddress((void**)&Hb, g_Hh);
    cudaGetSymbolAddress((void**)&Yb, g_Y);
    cudaGetSymbolAddress((void**)&Xr, g_Xr);
    cudaGetSymbolAddress((void**)&Wr, g_Wr);
    cudaGetSymbolAddress((void**)&Mbp, g_Mb);
    float* Wr0 = Wr;
    float* Wr1 = Wr + (size_t)Dd * Dd;
    float* Wr2 = Wr + (size_t)2 * Dd * Dd;
    float* Wr3 = Wr + (size_t)3 * Dd * Dd;

    cudaFuncSetAttribute(attn_mma_kernel, cudaFuncAttributeMaxDynamicSharedMemorySize, ATTN_SMEM_BYTES);
    cudaFuncSetAttribute(gemm_mma_kernel, cudaFuncAttributeMaxDynamicSharedMemorySize, GEMM_SMEM_BYTES);

    pack_mask_kernel<<<(Mm * NW) / 256, 256>>>(adj, Mbp);
    round_kernel<<<(Mm * Dd / 4) / 256, 256>>>(x, Xr);
    round_kernel<<<(Dd * Dd / 4) / 256, 256>>>(Wq, Wr0);
    round_kernel<<<(Dd * Dd / 4) / 256, 256>>>(Wk, Wr1);
    round_kernel<<<(Dd * Dd / 4) / 256, 256>>>(Wv, Wr2);
    round_kernel<<<(Dd * Dd / 4) / 256, 256>>>(Wo, Wr3);

    dim3 ggrid(Dd / GBN, Mm / GBM);   // (4, 64)
    gemm_mma_kernel<<<ggrid, 256, GEMM_SMEM_BYTES>>>(Xr, Wr0, bq, nullptr, Qb, Mm, Dd, Dd, 1);
    gemm_mma_kernel<<<ggrid, 256, GEMM_SMEM_BYTES>>>(Xr, Wr1, bk, nullptr, Kb, Mm, Dd, Dd, 1);
    gemm_mma_kernel<<<ggrid, 256, GEMM_SMEM_BYTES>>>(Xr, Wr2, bv, nullptr, Vb, Mm, Dd, Dd, 1);

    dim3 agrid(Nn / 128, Hh, Bb);     // (16, 8, 4)
    attn_mma_kernel<<<agrid, 256, ATTN_SMEM_BYTES>>>(Qb, Kb, Vb, Mbp, Hb);

    gemm_mma_kernel<<<ggrid, 256, GEMM_SMEM_BYTES>>>(Hb, Wr3, bo, x, Yb, Mm, Dd, Dd, 0);

    ln_kernel<<<Mm, 128>>>(Yb, gamma, beta, out);
}

// round 16
// speedup vs baseline: 1.2490x; 1.0063x over previous
#include <cuda_runtime.h>
#include <cstdint>
#include <math.h>

#define Bb 4
#define Nn 2048
#define Dd 512
#define Hh 8
#define HD 64
#define Mm (Bb * Nn)   // 8192
#define NW (Nn / 32)   // 64 mask words per row
#define QKS 1536       // row stride of fused QKV buffer
#define SC_LOG2E 0.18033688f   // 0.125 * log2(e)

// ---------------- scratch ----------------
__device__ float g_QKV[(size_t)Mm * QKS];      // fused Q|K|V, tf32-rounded
__device__ float g_Hh[(size_t)Mm * Dd];
__device__ float g_Y[(size_t)Mm * Dd];
__device__ float g_Xr[(size_t)Mm * Dd];        // tf32-rounded x
__device__ float g_Wcat[(size_t)Dd * QKS];     // tf32-rounded [Wq|Wk|Wv]
__device__ float g_Wor[(size_t)Dd * Dd];       // tf32-rounded Wo
__device__ float g_bcat[QKS];                  // [bq|bk|bv]
__device__ uint32_t g_Mb[(size_t)Mm * NW];     // bit-packed adjacency

// ---------------- helpers ----------------
__device__ __forceinline__ uint32_t smem_u32(const void* p) {
    uint32_t a;
    asm("{ .reg .u64 t; cvta.to.shared.u64 t, %1; cvt.u32.u64 %0, t; }" : "=r"(a) : "l"(p));
    return a;
}
__device__ __forceinline__ float ex2(float x) {
    float y; asm("ex2.approx.f32 %0, %1;" : "=f"(y) : "f"(x)); return y;
}
__device__ __forceinline__ float tf32r(float f) {
    uint32_t u; asm("cvt.rna.tf32.f32 %0, %1;" : "=r"(u) : "f"(f));
    return __uint_as_float(u);
}
__device__ __forceinline__ void mma_tf32(float* c, const uint32_t* a, const uint32_t* b) {
    asm volatile("mma.sync.aligned.m16n8k8.row.col.f32.tf32.tf32.f32 "
        "{%0,%1,%2,%3}, {%4,%5,%6,%7}, {%8,%9}, {%0,%1,%2,%3};"
        : "+f"(c[0]), "+f"(c[1]), "+f"(c[2]), "+f"(c[3])
        : "r"(a[0]), "r"(a[1]), "r"(a[2]), "r"(a[3]), "r"(b[0]), "r"(b[1]));
}
__device__ __forceinline__ void cpa16(uint32_t dst, const void* src) {
    asm volatile("cp.async.cg.shared.global [%0], [%1], 16;" :: "r"(dst), "l"(src));
}
#define CP_COMMIT() asm volatile("cp.async.commit_group;" ::: "memory")
#define CP_WAIT1()  asm volatile("cp.async.wait_group 1;" ::: "memory")
#define CP_WAIT0()  asm volatile("cp.async.wait_group 0;" ::: "memory")

// ---------------- prep kernels ----------------
__global__ void __launch_bounds__(256) round_kernel(
    const float* __restrict__ in, float* __restrict__ out)
{
    int i = blockIdx.x * 256 + threadIdx.x;
    float4 v = ((const float4*)in)[i];
    v.x = tf32r(v.x); v.y = tf32r(v.y); v.z = tf32r(v.z); v.w = tf32r(v.w);
    ((float4*)out)[i] = v;
}

// concat + round Wq|Wk|Wv -> Wcat[512][1536]
__global__ void __launch_bounds__(256) pack_w_kernel(
    const float* __restrict__ Wq, const float* __restrict__ Wk,
    const float* __restrict__ Wv, float* __restrict__ Wcat)
{
    int j = blockIdx.x * 256 + threadIdx.x;    // float4 index; 512*1536/4 total
    int row = j / (QKS / 4);
    int n = (j % (QKS / 4)) * 4;
    const float* src = (n < 512) ? Wq : ((n < 1024) ? Wk : Wv);
    float4 v = *(const float4*)(src + (size_t)row * Dd + (n & 511));
    v.x = tf32r(v.x); v.y = tf32r(v.y); v.z = tf32r(v.z); v.w = tf32r(v.w);
    ((float4*)Wcat)[j] = v;
}

__global__ void __launch_bounds__(384) pack_b_kernel(
    const float* __restrict__ bq, const float* __restrict__ bk,
    const float* __restrict__ bv, float* __restrict__ bcat)
{
    int j = threadIdx.x;                        // 384 float4
    int n = j * 4;
    const float* src = (n < 512) ? bq : ((n < 1024) ? bk : bv);
    ((float4*)bcat)[j] = *(const float4*)(src + (n & 511));
}

__global__ void __launch_bounds__(256) pack_mask_kernel(
    const int* __restrict__ adj, uint32_t* __restrict__ mb)
{
    int idx = blockIdx.x * 256 + threadIdx.x;   // word index
    const int4* src = (const int4*)(adj + (size_t)idx * 32);
    uint32_t w = 0;
#pragma unroll
    for (int i = 0; i < 8; i++) {
        int4 v = src[i];
        w |= (v.x != 0 ? 1u : 0u) << (4 * i + 0);
        w |= (v.y != 0 ? 1u : 0u) << (4 * i + 1);
        w |= (v.z != 0 ? 1u : 0u) << (4 * i + 2);
        w |= (v.w != 0 ? 1u : 0u) << (4 * i + 3);
    }
    mb[idx] = w;
}

// ======================================================================
// tf32 mma GEMM, cp.async 3-stage pipeline, ONE sync per k-iter.
// BM=128, BN=128, BK=32, 256 threads (8 warps 4x2), warp tile 32x64.
// Inputs pre-rounded to tf32.
// ======================================================================
#define GBM 128
#define GBN 128
#define GBK 32
#define ASTR 36
#define BSTR 132
#define GSM_BUF (GBM * ASTR + GBK * BSTR)   // 8832 floats per stage
#define GEMM_SMEM_BYTES (3 * GSM_BUF * 4)   // 105984

__global__ void __launch_bounds__(256, 2) gemm_mma_kernel(
    const float* __restrict__ A, const float* __restrict__ W,
    const float* __restrict__ bias, const float* __restrict__ resid,
    float* __restrict__ C, int M, int N, int K, int roundOut)
{
    extern __shared__ __align__(16) float gsm[];
    const uint32_t sbase = smem_u32(gsm);

    const int tid = threadIdx.x;
    const int wid = tid >> 5, lane = tid & 31;
    const int g = lane >> 2, q = lane & 3;
    const int wm = wid & 3, wn = wid >> 2;
    const int m0 = blockIdx.y * GBM;
    const int n0 = blockIdx.x * GBN;
    const int nk = K / GBK;

    const int ar0 = tid >> 3, ac0 = (tid & 7) * 4;    // A: 32 rows / pass
    const int wr0 = tid >> 5, wc0 = (tid & 31) * 4;   // W: 8 rows / pass

    auto issue = [&](int kt) {
        const int buf = kt % 3;
        const float* Ab = A + (size_t)m0 * K + kt * GBK;
        const uint32_t as = sbase + (uint32_t)(buf * GSM_BUF) * 4;
        const uint32_t ws = as + (uint32_t)(GBM * ASTR) * 4;
#pragma unroll
        for (int i = 0; i < 4; i++) {
            int r = i * 32 + ar0;
            cpa16(as + (uint32_t)(r * ASTR + ac0) * 4, Ab + (size_t)r * K + ac0);
        }
#pragma unroll
        for (int i = 0; i < 4; i++) {
            int r = i * 8 + wr0;
            cpa16(ws + (uint32_t)(r * BSTR + wc0) * 4, W + (size_t)(kt * GBK + r) * N + n0 + wc0);
        }
        CP_COMMIT();
    };

    float acc[2][8][4];
#pragma unroll
    for (int t = 0; t < 2; t++)
#pragma unroll
        for (int nb = 0; nb < 8; nb++)
#pragma unroll
            for (int i = 0; i < 4; i++) acc[t][nb][i] = 0.f;

    issue(0);
    if (nk > 1) issue(1);

#pragma unroll 1
    for (int kt = 0; kt < nk; kt++) {
        if (kt + 1 < nk) CP_WAIT1();   // stage kt complete (kt+1 may be in flight)
        else             CP_WAIT0();
        __syncthreads();               // stage kt visible; all warps done with kt-1
        if (kt + 2 < nk) issue(kt + 2);   // refills stage (kt+2)%3 == (kt-1)%3

        const float* As = gsm + (kt % 3) * GSM_BUF;
        const float* Ws = As + GBM * ASTR;

#pragma unroll
        for (int kk = 0; kk < 4; kk++) {
            uint32_t a[2][4];
#pragma unroll
            for (int t = 0; t < 2; t++) {
                const float* arp = As + (wm * 32 + 16 * t + g) * ASTR + 8 * kk + q;
                a[t][0] = __float_as_uint(arp[0]);
                a[t][1] = __float_as_uint(arp[8 * ASTR]);
                a[t][2] = __float_as_uint(arp[4]);
                a[t][3] = __float_as_uint(arp[8 * ASTR + 4]);
            }
            uint32_t bf[8][2];
#pragma unroll
            for (int nb = 0; nb < 8; nb++) {
                const float* brp = Ws + (8 * kk + q) * BSTR + wn * 64 + 8 * nb + g;
                bf[nb][0] = __float_as_uint(brp[0]);
                bf[nb][1] = __float_as_uint(brp[4 * BSTR]);
            }
#pragma unroll
            for (int t = 0; t < 2; t++)
#pragma unroll
                for (int nb = 0; nb < 8; nb++)
                    mma_tf32(acc[t][nb], a[t], bf[nb]);
        }
    }

#pragma unroll
    for (int t = 0; t < 2; t++) {
        const int r0 = m0 + wm * 32 + 16 * t + g;
#pragma unroll
        for (int nb = 0; nb < 8; nb++) {
            const int c = n0 + wn * 64 + 8 * nb + 2 * q;
            float bx = bias[c], by = bias[c + 1];
            float2 w0, w1;
            w0.x = acc[t][nb][0] + bx; w0.y = acc[t][nb][1] + by;
            w1.x = acc[t][nb][2] + bx; w1.y = acc[t][nb][3] + by;
            if (resid) {
                float2 r4 = *(const float2*)(resid + (size_t)r0 * N + c);
                float2 r5 = *(const float2*)(resid + (size_t)(r0 + 8) * N + c);
                w0.x += r4.x; w0.y += r4.y;
                w1.x += r5.x; w1.y += r5.y;
            }
            if (roundOut) {
                w0.x = tf32r(w0.x); w0.y = tf32r(w0.y);
                w1.x = tf32r(w1.x); w1.y = tf32r(w1.y);
            }
            *(float2*)(C + (size_t)r0 * N + c) = w0;
            *(float2*)(C + (size_t)(r0 + 8) * N + c) = w1;
        }
    }
}

// ======================================================================
// mma.sync tf32 attention (R15 measured-best; Q/K/V from fused QKV buffer)
// 128 queries/CTA, 256 threads (8 warps), 16 queries/warp, 2 CTAs/SM.
// ======================================================================
#define STR 68
#define OFF_Q 0
#define OFF_K (128 * STR)
#define OFF_V (192 * STR)
#define OFF_P (256 * STR)
#define ATTN_SMEM_FLOATS (384 * STR)            // 26112
#define ATTN_SMEM_BYTES (ATTN_SMEM_FLOATS * 4)  // 104448

__global__ void __launch_bounds__(256, 2) attn_mma_kernel(
    const float* __restrict__ QKV, const uint32_t* __restrict__ mb,
    float* __restrict__ O)
{
    extern __shared__ __align__(16) float sm[];
    const uint32_t sbase = smem_u32(sm);
    const int tid = threadIdx.x;
    const int wid = tid >> 5, lane = tid & 31;
    const int g = lane >> 2, q = lane & 3;
    const int h = blockIdx.y, b = blockIdx.z;
    const int q0 = blockIdx.x * 128;
    const unsigned FULL = 0xffffffffu;

    const int fr = tid >> 4, fc = (tid & 15) * 4;   // 16 rows per 256-thread pass

    const float* qgbase = QKV + ((size_t)(b * Nn + q0)) * QKS + h * HD;          // Q slice
    const float* kgbase = QKV + ((size_t)(b * Nn)) * QKS + 512 + h * HD;         // K slice
    const float* vgbase = QKV + ((size_t)(b * Nn)) * QKS + 1024 + h * HD;        // V slice
    const uint32_t* mrow0 = mb + (size_t)(b * Nn + q0 + wid * 16 + g) * NW;
    const uint32_t* mrow1 = mrow0 + (size_t)8 * NW;

    // ---- prologue: Q (group), K0 (group), V0 (group) via cp.async ----
    {
#pragma unroll
        for (int i = 0; i < 8; i++) {
            int r = i * 16 + fr;
            cpa16(sbase + (uint32_t)(OFF_Q + r * STR + fc) * 4, qgbase + (size_t)r * QKS + fc);
        }
        CP_COMMIT();
#pragma unroll
        for (int i = 0; i < 4; i++) {
            int r = i * 16 + fr;
            cpa16(sbase + (uint32_t)(OFF_K + r * STR + fc) * 4, kgbase + (size_t)r * QKS + fc);
        }
        CP_COMMIT();
#pragma unroll
        for (int i = 0; i < 4; i++) {
            int r = i * 16 + fr;
            cpa16(sbase + (uint32_t)(OFF_V + r * STR + fc) * 4, vgbase + (size_t)r * QKS + fc);
        }
        CP_COMMIT();
    }
    CP_WAIT1();          // Q + K0 complete; V0 may be in flight
    __syncthreads();

    float oacc[8][4];
#pragma unroll
    for (int n = 0; n < 8; n++)
#pragma unroll
        for (int i = 0; i < 4; i++) oacc[n][i] = 0.f;
    float lacc[2] = {0.f, 0.f};

    float* Pw = sm + OFF_P + wid * 16 * STR;
    const float* Ks = sm + OFF_K;
    const float* Vs = sm + OFF_V;

#pragma unroll 1
    for (int t64 = 0; t64 < 32; t64++) {
        const int k0 = t64 * 64;

        // ---- S = Q(16x64) @ K^T(64x64) per warp: 64 mma ----
        float sacc[8][4];
#pragma unroll
        for (int n = 0; n < 8; n++)
#pragma unroll
            for (int i = 0; i < 4; i++) sacc[n][i] = 0.f;

#pragma unroll
        for (int kk = 0; kk < 8; kk++) {
            uint32_t a[4];
            {
                const float* qrow = sm + OFF_Q + (wid * 16 + g) * STR + 8 * kk + q;
                a[0] = __float_as_uint(qrow[0]);
                a[1] = __float_as_uint(qrow[8 * STR]);
                a[2] = __float_as_uint(qrow[4]);
                a[3] = __float_as_uint(qrow[8 * STR + 4]);
            }
            uint32_t bf[8][2];
#pragma unroll
            for (int n = 0; n < 8; n++) {
                const float* krow = Ks + (8 * n + g) * STR + 8 * kk + q;
                bf[n][0] = __float_as_uint(krow[0]);
                bf[n][1] = __float_as_uint(krow[4]);
            }
#pragma unroll
            for (int n = 0; n < 8; n++)
                mma_tf32(sacc[n], a, bf[n]);
        }

        __syncthreads();   // all warps done reading K[t]
        if (t64 + 1 < 32) {
            const float* kg = kgbase + (size_t)(k0 + 64) * QKS;
#pragma unroll
            for (int i = 0; i < 4; i++) {
                int r = i * 16 + fr;
                cpa16(sbase + (uint32_t)(OFF_K + r * STR + fc) * 4, kg + (size_t)r * QKS + fc);
            }
            CP_COMMIT();   // outstanding: V[t], K[t+1]
        }

        // ---- softmax: P = maskbit * exp2(S*sc); row sums; store P ----
        {
            uint2 w0 = *(const uint2*)(mrow0 + (k0 >> 5));   // keys [k0, k0+64)
            uint2 w1 = *(const uint2*)(mrow1 + (k0 >> 5));
            float l0 = 0.f, l1 = 0.f;
#pragma unroll
            for (int n = 0; n < 8; n++) {
                const uint32_t u0 = (n < 4) ? w0.x : w0.y;
                const uint32_t u1 = (n < 4) ? w1.x : w1.y;
                const int j = 8 * (n & 3) + 2 * q;
                float p0 = ((u0 >> j) & 1u)       ? ex2(sacc[n][0] * SC_LOG2E) : 0.f;
                float p1 = ((u0 >> (j + 1)) & 1u) ? ex2(sacc[n][1] * SC_LOG2E) : 0.f;
                float p2 = ((u1 >> j) & 1u)       ? ex2(sacc[n][2] * SC_LOG2E) : 0.f;
                float p3 = ((u1 >> (j + 1)) & 1u) ? ex2(sacc[n][3] * SC_LOG2E) : 0.f;
                l0 += p0 + p1; l1 += p2 + p3;
                float2 s0; s0.x = tf32r(p0); s0.y = tf32r(p1);
                float2 s1; s1.x = tf32r(p2); s1.y = tf32r(p3);
                *(float2*)(Pw + g * STR + 8 * n + 2 * q) = s0;
                *(float2*)(Pw + (g + 8) * STR + 8 * n + 2 * q) = s1;
            }
            lacc[0] += l0;
            lacc[1] += l1;
        }

        if (t64 + 1 < 32) CP_WAIT1();   // V[t] (oldest) complete
        else              CP_WAIT0();
        __syncthreads();                // V[t] visible

        // ---- O += P(16x64) @ V(64x64): 64 mma ----
#pragma unroll
        for (int kk = 0; kk < 8; kk++) {
            uint32_t a[4];
            {
                const float* prow = Pw + g * STR + 8 * kk + q;
                a[0] = __float_as_uint(prow[0]);
                a[1] = __float_as_uint(prow[8 * STR]);
                a[2] = __float_as_uint(prow[4]);
                a[3] = __float_as_uint(prow[8 * STR + 4]);
            }
            uint32_t bf[8][2];
#pragma unroll
            for (int n = 0; n < 8; n++) {
                const float* vrow = Vs + (8 * kk + q) * STR + 8 * n + g;
                bf[n][0] = __float_as_uint(vrow[0]);
                bf[n][1] = __float_as_uint(vrow[4 * STR]);
            }
#pragma unroll
            for (int n = 0; n < 8; n++)
                mma_tf32(oacc[n], a, bf[n]);
        }

        if (t64 + 1 < 32) {
            __syncthreads();   // all warps done reading V[t]
            const float* vg = vgbase + (size_t)(k0 + 64) * QKS;
#pragma unroll
            for (int i = 0; i < 4; i++) {
                int r = i * 16 + fr;
                cpa16(sbase + (uint32_t)(OFF_V + r * STR + fc) * 4, vg + (size_t)r * QKS + fc);
            }
            CP_COMMIT();       // outstanding: K[t+1], V[t+1]
            CP_WAIT1();        // K[t+1] complete
            __syncthreads();   // K[t+1] visible
        }
    }

    // ---- reduce row sums across the quad ----
#pragma unroll
    for (int i = 0; i < 2; i++) {
        lacc[i] += __shfl_xor_sync(FULL, lacc[i], 1);
        lacc[i] += __shfl_xor_sync(FULL, lacc[i], 2);
    }
    const float inv0 = 1.f / lacc[0];
    const float inv1 = 1.f / lacc[1];

    // ---- write H (tf32-rounded: consumed by cp.async Wo GEMM) ----
    float* og = O + ((size_t)(b * Nn + q0 + wid * 16)) * Dd + h * HD;
#pragma unroll
    for (int n = 0; n < 8; n++) {
        float2 w0;
        w0.x = tf32r(oacc[n][0] * inv0);
        w0.y = tf32r(oacc[n][1] * inv0);
        *(float2*)(og + (size_t)g * Dd + 8 * n + 2 * q) = w0;
        float2 w1;
        w1.x = tf32r(oacc[n][2] * inv1);
        w1.y = tf32r(oacc[n][3] * inv1);
        *(float2*)(og + (size_t)(g + 8) * Dd + 8 * n + 2 * q) = w1;
    }
}

// ================= LayerNorm (unchanged) =================
__global__ __launch_bounds__(128) void ln_kernel(
    const float* __restrict__ Y, const float* __restrict__ gamma,
    const float* __restrict__ beta, float* __restrict__ out)
{
    __shared__ float sbuf[4];
    __shared__ float smu, srstd;
    const int tid = threadIdx.x;
    const int row = blockIdx.x;
    const float* y = Y + (size_t)row * Dd;

    float4 v = ((const float4*)y)[tid];
    float sum = v.x + v.y + v.z + v.w;
    int lane = tid & 31, wid = tid >> 5;
#pragma unroll
    for (int off = 16; off > 0; off >>= 1) sum += __shfl_xor_sync(0xffffffffu, sum, off);
    if (lane == 0) sbuf[wid] = sum;
    __syncthreads();
    if (tid == 0) smu = (sbuf[0] + sbuf[1] + sbuf[2] + sbuf[3]) * (1.f / Dd);
    __syncthreads();
    float mu = smu;

    float dx = v.x - mu, dy = v.y - mu, dz = v.z - mu, dw = v.w - mu;
    float sq = dx * dx + dy * dy + dz * dz + dw * dw;
#pragma unroll
    for (int off = 16; off > 0; off >>= 1) sq += __shfl_xor_sync(0xffffffffu, sq, off);
    __syncthreads();
    if (lane == 0) sbuf[wid] = sq;
    __syncthreads();
    if (tid == 0) {
        float var = (sbuf[0] + sbuf[1] + sbuf[2] + sbuf[3]) * (1.f / Dd);
        srstd = rsqrtf(var + 1e-5f);
    }
    __syncthreads();
    float rstd = srstd;

    int c = tid * 4;
    float4 g = *(const float4*)(gamma + c);
    float4 be = *(const float4*)(beta + c);
    float4 r;
    r.x = dx * rstd * g.x + be.x;
    r.y = dy * rstd * g.y + be.y;
    r.z = dz * rstd * g.z + be.z;
    r.w = dw * rstd * g.w + be.w;
    ((float4*)(out + (size_t)row * Dd))[tid] = r;
}

// ================= launch =================
extern "C" void kernel_launch(void* const* d_in, const int* in_sizes, int n_in,
                              void* d_out, int out_size)
{
    const float* x     = (const float*)d_in[0];
    const int*   adj   = (const int*)d_in[1];
    const float* Wq    = (const float*)d_in[2];
    const float* bq    = (const float*)d_in[3];
    const float* Wk    = (const float*)d_in[4];
    const float* bk    = (const float*)d_in[5];
    const float* Wv    = (const float*)d_in[6];
    const float* bv    = (const float*)d_in[7];
    const float* Wo    = (const float*)d_in[8];
    const float* bo    = (const float*)d_in[9];
    const float* gamma = (const float*)d_in[10];
    const float* beta  = (const float*)d_in[11];
    float* out = (float*)d_out;

    float *QKVb, *Hb, *Yb, *Xr, *Wcat, *Wor, *bcat;
    uint32_t* Mbp;
    cudaGetSymbolAddress((void**)&QKVb, g_QKV);
    cudaGetSymbolAddress((void**)&Hb, g_Hh);
    cudaGetSymbolAddress((void**)&Yb, g_Y);
    cudaGetSymbolAddress((void**)&Xr, g_Xr);
    cudaGetSymbolAddress((void**)&Wcat, g_Wcat);
    cudaGetSymbolAddress((void**)&Wor, g_Wor);
    cudaGetSymbolAddress((void**)&bcat, g_bcat);
    cudaGetSymbolAddress((void**)&Mbp, g_Mb);

    cudaFuncSetAttribute(attn_mma_kernel, cudaFuncAttributeMaxDynamicSharedMemorySize, ATTN_SMEM_BYTES);
    cudaFuncSetAttribute(gemm_mma_kernel, cudaFuncAttributeMaxDynamicSharedMemorySize, GEMM_SMEM_BYTES);

    pack_mask_kernel<<<(Mm * NW) / 256, 256>>>(adj, Mbp);
    round_kernel<<<(Mm * Dd / 4) / 256, 256>>>(x, Xr);
    round_kernel<<<(Dd * Dd / 4) / 256, 256>>>(Wo, Wor);
    pack_w_kernel<<<(Dd * QKS / 4) / 256, 256>>>(Wq, Wk, Wv, Wcat);
    pack_b_kernel<<<1, 384>>>(bq, bk, bv, bcat);

    // fused QKV projection: C[8192][1536]
    dim3 qgrid(QKS / GBN, Mm / GBM);   // (12, 64) = 768 CTAs
    gemm_mma_kernel<<<qgrid, 256, GEMM_SMEM_BYTES>>>(Xr, Wcat, bcat, nullptr, QKVb, Mm, QKS, Dd, 1);

    dim3 agrid(Nn / 128, Hh, Bb);      // (16, 8, 4)
    attn_mma_kernel<<<agrid, 256, ATTN_SMEM_BYTES>>>(QKVb, Mbp, Hb);

    dim3 ogrid(Dd / GBN, Mm / GBM);    // (4, 64)
    gemm_mma_kernel<<<ogrid, 256, GEMM_SMEM_BYTES>>>(Hb, Wor, bo, x, Yb, Mm, Dd, Dd, 0);

    ln_kernel<<<Mm, 128>>>(Yb, gamma, beta, out);
}

// round 17
// speedup vs baseline: 1.8216x; 1.4585x over previous
#include <cuda_runtime.h>
#include <cuda_bf16.h>
#include <cstdint>
#include <math.h>

#define Bb 4
#define Nn 2048
#define Dd 512
#define Hh 8
#define HD 64
#define Mm (Bb * Nn)   // 8192
#define NW (Nn / 32)   // 64 mask words per row
#define QKS 1536       // row stride (halves) of fused QKV bf16 buffer
#define SC_LOG2E 0.18033688f   // 0.125 * log2(e)

// ---------------- scratch ----------------
__device__ __nv_bfloat16 g_QKVh[(size_t)Mm * QKS];        // fused Q|K|V bf16
__device__ __nv_bfloat16 g_Vt[(size_t)Bb * Dd * Nn];      // V^T bf16 [b][dim][key]
__device__ float g_Hh[(size_t)Mm * Dd];
__device__ float g_Y[(size_t)Mm * Dd];
__device__ float g_Xr[(size_t)Mm * Dd];                   // tf32-rounded x
__device__ float g_Wcat[(size_t)Dd * QKS];                // tf32-rounded [Wq|Wk|Wv]
__device__ float g_Wor[(size_t)Dd * Dd];                  // tf32-rounded Wo
__device__ float g_bcat[QKS];                             // [bq|bk|bv]
__device__ uint32_t g_Mb[(size_t)Mm * NW];                // bit-packed adjacency

// ---------------- helpers ----------------
__device__ __forceinline__ uint32_t smem_u32(const void* p) {
    uint32_t a;
    asm("{ .reg .u64 t; cvta.to.shared.u64 t, %1; cvt.u32.u64 %0, t; }" : "=r"(a) : "l"(p));
    return a;
}
__device__ __forceinline__ float ex2(float x) {
    float y; asm("ex2.approx.f32 %0, %1;" : "=f"(y) : "f"(x)); return y;
}
__device__ __forceinline__ float tf32r(float f) {
    uint32_t u; asm("cvt.rna.tf32.f32 %0, %1;" : "=r"(u) : "f"(f));
    return __uint_as_float(u);
}
__device__ __forceinline__ uint32_t bf16pack(float lo, float hi) {
    uint32_t r;
    asm("cvt.rn.bf16x2.f32 %0, %1, %2;" : "=r"(r) : "f"(hi), "f"(lo));
    return r;
}
__device__ __forceinline__ void mma_tf32(float* c, const uint32_t* a, const uint32_t* b) {
    asm volatile("mma.sync.aligned.m16n8k8.row.col.f32.tf32.tf32.f32 "
        "{%0,%1,%2,%3}, {%4,%5,%6,%7}, {%8,%9}, {%0,%1,%2,%3};"
        : "+f"(c[0]), "+f"(c[1]), "+f"(c[2]), "+f"(c[3])
        : "r"(a[0]), "r"(a[1]), "r"(a[2]), "r"(a[3]), "r"(b[0]), "r"(b[1]));
}
__device__ __forceinline__ void mma_bf16(float* c, const uint32_t* a, const uint32_t* b) {
    asm volatile("mma.sync.aligned.m16n8k16.row.col.f32.bf16.bf16.f32 "
        "{%0,%1,%2,%3}, {%4,%5,%6,%7}, {%8,%9}, {%0,%1,%2,%3};"
        : "+f"(c[0]), "+f"(c[1]), "+f"(c[2]), "+f"(c[3])
        : "r"(a[0]), "r"(a[1]), "r"(a[2]), "r"(a[3]), "r"(b[0]), "r"(b[1]));
}
__device__ __forceinline__ void cpa16(uint32_t dst, const void* src) {
    asm volatile("cp.async.cg.shared.global [%0], [%1], 16;" :: "r"(dst), "l"(src));
}
#define CP_COMMIT() asm volatile("cp.async.commit_group;" ::: "memory")
#define CP_WAIT1()  asm volatile("cp.async.wait_group 1;" ::: "memory")
#define CP_WAIT0()  asm volatile("cp.async.wait_group 0;" ::: "memory")

// ---------------- prep kernels ----------------
__global__ void __launch_bounds__(256) round_kernel(
    const float* __restrict__ in, float* __restrict__ out)
{
    int i = blockIdx.x * 256 + threadIdx.x;
    float4 v = ((const float4*)in)[i];
    v.x = tf32r(v.x); v.y = tf32r(v.y); v.z = tf32r(v.z); v.w = tf32r(v.w);
    ((float4*)out)[i] = v;
}

__global__ void __launch_bounds__(256) pack_w_kernel(
    const float* __restrict__ Wq, const float* __restrict__ Wk,
    const float* __restrict__ Wv, float* __restrict__ Wcat)
{
    int j = blockIdx.x * 256 + threadIdx.x;    // float4 index
    int row = j / (QKS / 4);
    int n = (j % (QKS / 4)) * 4;
    const float* src = (n < 512) ? Wq : ((n < 1024) ? Wk : Wv);
    float4 v = *(const float4*)(src + (size_t)row * Dd + (n & 511));
    v.x = tf32r(v.x); v.y = tf32r(v.y); v.z = tf32r(v.z); v.w = tf32r(v.w);
    ((float4*)Wcat)[j] = v;
}

__global__ void __launch_bounds__(384) pack_b_kernel(
    const float* __restrict__ bq, const float* __restrict__ bk,
    const float* __restrict__ bv, float* __restrict__ bcat)
{
    int j = threadIdx.x;
    int n = j * 4;
    const float* src = (n < 512) ? bq : ((n < 1024) ? bk : bv);
    ((float4*)bcat)[j] = *(const float4*)(src + (n & 511));
}

__global__ void __launch_bounds__(256) pack_mask_kernel(
    const int* __restrict__ adj, uint32_t* __restrict__ mb)
{
    int idx = blockIdx.x * 256 + threadIdx.x;
    const int4* src = (const int4*)(adj + (size_t)idx * 32);
    uint32_t w = 0;
#pragma unroll
    for (int i = 0; i < 8; i++) {
        int4 v = src[i];
        w |= (v.x != 0 ? 1u : 0u) << (4 * i + 0);
        w |= (v.y != 0 ? 1u : 0u) << (4 * i + 1);
        w |= (v.z != 0 ? 1u : 0u) << (4 * i + 2);
        w |= (v.w != 0 ? 1u : 0u) << (4 * i + 3);
    }
    mb[idx] = w;
}

// V-slice transpose: QKVh[:, 1024:1536] (bf16) -> Vt[b][dim 512][key 2048]
// grid (32 token-tiles, 8 dim-tiles, 4 b), 256 threads, 64x64 tiles.
__global__ void __launch_bounds__(256) transpose_v_kernel(
    const __nv_bfloat16* __restrict__ qkv, __nv_bfloat16* __restrict__ vt)
{
    __shared__ __nv_bfloat16 tile[64][72];
    const int tid = threadIdx.x;
    const int t0 = blockIdx.x * 64, d0 = blockIdx.y * 64, b = blockIdx.z;

    // read: 64 tokens x 64 dims (u32 = 2 dims per load)
#pragma unroll
    for (int p = 0; p < 8; p++) {
        int idx = p * 256 + tid;
        int r = idx >> 5, cu = idx & 31;
        uint32_t v = *(const uint32_t*)(qkv + ((size_t)(b * Nn + t0 + r)) * QKS + 1024 + d0 + 2 * cu);
        *(uint32_t*)&tile[r][2 * cu] = v;
    }
    __syncthreads();

    // write: 64 dims x 64 tokens (u32 = 2 tokens packed)
#pragma unroll
    for (int p = 0; p < 8; p++) {
        int idx = p * 256 + tid;
        int d = idx >> 5, cu = idx & 31;
        uint32_t lo = ((const uint16_t(&)[72])tile[2 * cu])[d];
        uint32_t hi = ((const uint16_t(&)[72])tile[2 * cu + 1])[d];
        *(uint32_t*)(vt + ((size_t)(b * Dd + d0 + d)) * Nn + t0 + 2 * cu) = lo | (hi << 16);
    }
}

// ======================================================================
// tf32 mma GEMM, cp.async 3-stage, 1 sync/iter.
// outMode: 0 = fp32 (+resid), 2 = bf16 packed.
// ======================================================================
#define GBM 128
#define GBN 128
#define GBK 32
#define ASTR 36
#define BSTR 132
#define GSM_BUF (GBM * ASTR + GBK * BSTR)   // 8832 floats per stage
#define GEMM_SMEM_BYTES (3 * GSM_BUF * 4)   // 105984

__global__ void __launch_bounds__(256, 2) gemm_mma_kernel(
    const float* __restrict__ A, const float* __restrict__ W,
    const float* __restrict__ bias, const float* __restrict__ resid,
    void* __restrict__ Cout, int M, int N, int K, int outMode)
{
    extern __shared__ __align__(16) float gsm[];
    const uint32_t sbase = smem_u32(gsm);

    const int tid = threadIdx.x;
    const int wid = tid >> 5, lane = tid & 31;
    const int g = lane >> 2, q = lane & 3;
    const int wm = wid & 3, wn = wid >> 2;
    const int m0 = blockIdx.y * GBM;
    const int n0 = blockIdx.x * GBN;
    const int nk = K / GBK;

    const int ar0 = tid >> 3, ac0 = (tid & 7) * 4;
    const int wr0 = tid >> 5, wc0 = (tid & 31) * 4;

    auto issue = [&](int kt) {
        const int buf = kt % 3;
        const float* Ab = A + (size_t)m0 * K + kt * GBK;
        const uint32_t as = sbase + (uint32_t)(buf * GSM_BUF) * 4;
        const uint32_t ws = as + (uint32_t)(GBM * ASTR) * 4;
#pragma unroll
        for (int i = 0; i < 4; i++) {
            int r = i * 32 + ar0;
            cpa16(as + (uint32_t)(r * ASTR + ac0) * 4, Ab + (size_t)r * K + ac0);
        }
#pragma unroll
        for (int i = 0; i < 4; i++) {
            int r = i * 8 + wr0;
            cpa16(ws + (uint32_t)(r * BSTR + wc0) * 4, W + (size_t)(kt * GBK + r) * N + n0 + wc0);
        }
        CP_COMMIT();
    };

    float acc[2][8][4];
#pragma unroll
    for (int t = 0; t < 2; t++)
#pragma unroll
        for (int nb = 0; nb < 8; nb++)
#pragma unroll
            for (int i = 0; i < 4; i++) acc[t][nb][i] = 0.f;

    issue(0);
    if (nk > 1) issue(1);

#pragma unroll 1
    for (int kt = 0; kt < nk; kt++) {
        if (kt + 1 < nk) CP_WAIT1();
        else             CP_WAIT0();
        __syncthreads();
        if (kt + 2 < nk) issue(kt + 2);

        const float* As = gsm + (kt % 3) * GSM_BUF;
        const float* Ws = As + GBM * ASTR;

#pragma unroll
        for (int kk = 0; kk < 4; kk++) {
            uint32_t a[2][4];
#pragma unroll
            for (int t = 0; t < 2; t++) {
                const float* arp = As + (wm * 32 + 16 * t + g) * ASTR + 8 * kk + q;
                a[t][0] = __float_as_uint(arp[0]);
                a[t][1] = __float_as_uint(arp[8 * ASTR]);
                a[t][2] = __float_as_uint(arp[4]);
                a[t][3] = __float_as_uint(arp[8 * ASTR + 4]);
            }
            uint32_t bf[8][2];
#pragma unroll
            for (int nb = 0; nb < 8; nb++) {
                const float* brp = Ws + (8 * kk + q) * BSTR + wn * 64 + 8 * nb + g;
                bf[nb][0] = __float_as_uint(brp[0]);
                bf[nb][1] = __float_as_uint(brp[4 * BSTR]);
            }
#pragma unroll
            for (int t = 0; t < 2; t++)
#pragma unroll
                for (int nb = 0; nb < 8; nb++)
                    mma_tf32(acc[t][nb], a[t], bf[nb]);
        }
    }

#pragma unroll
    for (int t = 0; t < 2; t++) {
        const int r0 = m0 + wm * 32 + 16 * t + g;
#pragma unroll
        for (int nb = 0; nb < 8; nb++) {
            const int c = n0 + wn * 64 + 8 * nb + 2 * q;
            float bx = bias[c], by = bias[c + 1];
            float2 w0, w1;
            w0.x = acc[t][nb][0] + bx; w0.y = acc[t][nb][1] + by;
            w1.x = acc[t][nb][2] + bx; w1.y = acc[t][nb][3] + by;
            if (outMode == 2) {
                __nv_bfloat16* C = (__nv_bfloat16*)Cout;
                *(uint32_t*)(C + (size_t)r0 * N + c) = bf16pack(w0.x, w0.y);
                *(uint32_t*)(C + (size_t)(r0 + 8) * N + c) = bf16pack(w1.x, w1.y);
            } else {
                float* C = (float*)Cout;
                if (resid) {
                    float2 r4 = *(const float2*)(resid + (size_t)r0 * N + c);
                    float2 r5 = *(const float2*)(resid + (size_t)(r0 + 8) * N + c);
                    w0.x += r4.x; w0.y += r4.y;
                    w1.x += r5.x; w1.y += r5.y;
                }
                *(float2*)(C + (size_t)r0 * N + c) = w0;
                *(float2*)(C + (size_t)(r0 + 8) * N + c) = w1;
            }
        }
    }
}

// ======================================================================
// bf16 mma attention: 128 queries/CTA, 256 threads (8 warps), 16 q/warp,
// double-buffered K/V, one sync + one wait per tile, 2 CTAs/SM.
// ======================================================================
#define HSTR 72   // smem row stride in halves (144B): bank = 4g+q, conflict-free
#define OFF_Q 0
#define OFF_K(buf) (128 * HSTR + (buf) * 64 * HSTR)
#define OFF_V(buf) (256 * HSTR + (buf) * 64 * HSTR)
#define OFF_P (384 * HSTR)
#define ATTN_SMEM_HALVES (512 * HSTR)               // 36864
#define ATTN_SMEM_BYTES (ATTN_SMEM_HALVES * 2)      // 73728

__global__ void __launch_bounds__(256, 2) attn_mma_kernel(
    const __nv_bfloat16* __restrict__ QKV, const __nv_bfloat16* __restrict__ Vt,
    const uint32_t* __restrict__ mb, float* __restrict__ O)
{
    extern __shared__ __align__(16) uint16_t smh[];
    const uint32_t sbase = smem_u32(smh);
    const int tid = threadIdx.x;
    const int wid = tid >> 5, lane = tid & 31;
    const int g = lane >> 2, q = lane & 3;
    const int h = blockIdx.y, b = blockIdx.z;
    const int q0 = blockIdx.x * 128;
    const unsigned FULL = 0xffffffffu;

    const int fr = tid >> 3, fc = (tid & 7) * 8;   // 32 rows per 256-thread pass, 8 halves/seg

    const __nv_bfloat16* qgbase = QKV + ((size_t)(b * Nn + q0)) * QKS + h * HD;
    const __nv_bfloat16* kgbase = QKV + ((size_t)(b * Nn)) * QKS + 512 + h * HD;
    const __nv_bfloat16* vtbase = Vt + ((size_t)(b * Dd + h * HD)) * Nn;
    const uint32_t* mrow0 = mb + (size_t)(b * Nn + q0 + wid * 16 + g) * NW;
    const uint32_t* mrow1 = mrow0 + (size_t)8 * NW;

    // ---- prologue: Q + K0 + V0, one commit group ----
    {
#pragma unroll
        for (int i = 0; i < 4; i++) {
            int r = i * 32 + fr;
            cpa16(sbase + (uint32_t)(OFF_Q + r * HSTR + fc) * 2, qgbase + (size_t)r * QKS + fc);
        }
#pragma unroll
        for (int i = 0; i < 2; i++) {
            int r = i * 32 + fr;
            cpa16(sbase + (uint32_t)(OFF_K(0) + r * HSTR + fc) * 2, kgbase + (size_t)r * QKS + fc);
            cpa16(sbase + (uint32_t)(OFF_V(0) + r * HSTR + fc) * 2, vtbase + (size_t)r * Nn + fc);
        }
        CP_COMMIT();
    }

    float oacc[8][4];
#pragma unroll
    for (int n = 0; n < 8; n++)
#pragma unroll
        for (int i = 0; i < 4; i++) oacc[n][i] = 0.f;
    float lacc[2] = {0.f, 0.f};

    uint16_t* Ph = smh + OFF_P + wid * 16 * HSTR;

#pragma unroll 1
    for (int t64 = 0; t64 < 32; t64++) {
        const int buf = t64 & 1;
        const int k0 = t64 * 64;

        CP_WAIT0();        // tile t data complete
        __syncthreads();   // visible to all; all warps done with bufs of t-1

        if (t64 + 1 < 32) {
            const __nv_bfloat16* kg = kgbase + (size_t)(k0 + 64) * QKS;
            const __nv_bfloat16* vg = vtbase + (k0 + 64);
            const int ob = buf ^ 1;
#pragma unroll
            for (int i = 0; i < 2; i++) {
                int r = i * 32 + fr;
                cpa16(sbase + (uint32_t)(OFF_K(ob) + r * HSTR + fc) * 2, kg + (size_t)r * QKS + fc);
                cpa16(sbase + (uint32_t)(OFF_V(ob) + r * HSTR + fc) * 2, vg + (size_t)r * Nn + fc);
            }
            CP_COMMIT();
        }

        const uint16_t* Ks = smh + OFF_K(buf);
        const uint16_t* Vs = smh + OFF_V(buf);

        // ---- S = Q(16x64) @ K^T(64x64): 32 bf16 mma ----
        float sacc[8][4];
#pragma unroll
        for (int n = 0; n < 8; n++)
#pragma unroll
            for (int i = 0; i < 4; i++) sacc[n][i] = 0.f;

#pragma unroll
        for (int kk = 0; kk < 4; kk++) {
            uint32_t a[4];
            {
                const uint16_t* qrow = smh + OFF_Q + (wid * 16 + g) * HSTR + 16 * kk + 2 * q;
                a[0] = *(const uint32_t*)(qrow);
                a[1] = *(const uint32_t*)(qrow + 8 * HSTR);
                a[2] = *(const uint32_t*)(qrow + 8);
                a[3] = *(const uint32_t*)(qrow + 8 * HSTR + 8);
            }
#pragma unroll
            for (int n = 0; n < 8; n++) {
                const uint16_t* krow = Ks + (8 * n + g) * HSTR + 16 * kk + 2 * q;
                uint32_t bf[2];
                bf[0] = *(const uint32_t*)(krow);
                bf[1] = *(const uint32_t*)(krow + 8);
                mma_bf16(sacc[n], a, bf);
            }
        }

        // ---- softmax: P = maskbit * exp2(S*sc); row sums; store P bf16 ----
        {
            uint2 w0 = *(const uint2*)(mrow0 + (k0 >> 5));
            uint2 w1 = *(const uint2*)(mrow1 + (k0 >> 5));
            float l0 = 0.f, l1 = 0.f;
#pragma unroll
            for (int n = 0; n < 8; n++) {
                const uint32_t u0 = (n < 4) ? w0.x : w0.y;
                const uint32_t u1 = (n < 4) ? w1.x : w1.y;
                const int j = 8 * (n & 3) + 2 * q;
                float p0 = ((u0 >> j) & 1u)       ? ex2(sacc[n][0] * SC_LOG2E) : 0.f;
                float p1 = ((u0 >> (j + 1)) & 1u) ? ex2(sacc[n][1] * SC_LOG2E) : 0.f;
                float p2 = ((u1 >> j) & 1u)       ? ex2(sacc[n][2] * SC_LOG2E) : 0.f;
                float p3 = ((u1 >> (j + 1)) & 1u) ? ex2(sacc[n][3] * SC_LOG2E) : 0.f;
                l0 += p0 + p1; l1 += p2 + p3;
                *(uint32_t*)(Ph + g * HSTR + 8 * n + 2 * q) = bf16pack(p0, p1);
                *(uint32_t*)(Ph + (g + 8) * HSTR + 8 * n + 2 * q) = bf16pack(p2, p3);
            }
            lacc[0] += l0;
            lacc[1] += l1;
        }
        __syncwarp();

        // ---- O += P(16x64) @ V(64x64): 32 bf16 mma ----
#pragma unroll
        for (int kk = 0; kk < 4; kk++) {
            uint32_t a[4];
            {
                const uint16_t* prow = Ph + g * HSTR + 16 * kk + 2 * q;
                a[0] = *(const uint32_t*)(prow);
                a[1] = *(const uint32_t*)(prow + 8 * HSTR);
                a[2] = *(const uint32_t*)(prow + 8);
                a[3] = *(const uint32_t*)(prow + 8 * HSTR + 8);
            }
#pragma unroll
            for (int n = 0; n < 8; n++) {
                const uint16_t* vrow = Vs + (8 * n + g) * HSTR + 16 * kk + 2 * q;
                uint32_t bf[2];
                bf[0] = *(const uint32_t*)(vrow);
                bf[1] = *(const uint32_t*)(vrow + 8);
                mma_bf16(oacc[n], a, bf);
            }
        }
        __syncwarp();
    }

    // ---- reduce row sums across the quad ----
#pragma unroll
    for (int i = 0; i < 2; i++) {
        lacc[i] += __shfl_xor_sync(FULL, lacc[i], 1);
        lacc[i] += __shfl_xor_sync(FULL, lacc[i], 2);
    }
    const float inv0 = 1.f / lacc[0];
    const float inv1 = 1.f / lacc[1];

    // ---- write H (fp32, tf32-rounded for the Wo GEMM) ----
    float* og = O + ((size_t)(b * Nn + q0 + wid * 16)) * Dd + h * HD;
#pragma unroll
    for (int n = 0; n < 8; n++) {
        float2 w0;
        w0.x = tf32r(oacc[n][0] * inv0);
        w0.y = tf32r(oacc[n][1] * inv0);
        *(float2*)(og + (size_t)g * Dd + 8 * n + 2 * q) = w0;
        float2 w1;
        w1.x = tf32r(oacc[n][2] * inv1);
        w1.y = tf32r(oacc[n][3] * inv1);
        *(float2*)(og + (size_t)(g + 8) * Dd + 8 * n + 2 * q) = w1;
    }
}

// ================= LayerNorm (unchanged) =================
__global__ __launch_bounds__(128) void ln_kernel(
    const float* __restrict__ Y, const float* __restrict__ gamma,
    const float* __restrict__ beta, float* __restrict__ out)
{
    __shared__ float sbuf[4];
    __shared__ float smu, srstd;
    const int tid = threadIdx.x;
    const int row = blockIdx.x;
    const float* y = Y + (size_t)row * Dd;

    float4 v = ((const float4*)y)[tid];
    float sum = v.x + v.y + v.z + v.w;
    int lane = tid & 31, wid = tid >> 5;
#pragma unroll
    for (int off = 16; off > 0; off >>= 1) sum += __shfl_xor_sync(0xffffffffu, sum, off);
    if (lane == 0) sbuf[wid] = sum;
    __syncthreads();
    if (tid == 0) smu = (sbuf[0] + sbuf[1] + sbuf[2] + sbuf[3]) * (1.f / Dd);
    __syncthreads();
    float mu = smu;

    float dx = v.x - mu, dy = v.y - mu, dz = v.z - mu, dw = v.w - mu;
    float sq = dx * dx + dy * dy + dz * dz + dw * dw;
#pragma unroll
    for (int off = 16; off > 0; off >>= 1) sq += __shfl_xor_sync(0xffffffffu, sq, off);
    __syncthreads();
    if (lane == 0) sbuf[wid] = sq;
    __syncthreads();
    if (tid == 0) {
        float var = (sbuf[0] + sbuf[1] + sbuf[2] + sbuf[3]) * (1.f / Dd);
        srstd = rsqrtf(var + 1e-5f);
    }
    __syncthreads();
    float rstd = srstd;

    int c = tid * 4;
    float4 g = *(const float4*)(gamma + c);
    float4 be = *(const float4*)(beta + c);
    float4 r;
    r.x = dx * rstd * g.x + be.x;
    r.y = dy * rstd * g.y + be.y;
    r.z = dz * rstd * g.z + be.z;
    r.w = dw * rstd * g.w + be.w;
    ((float4*)(out + (size_t)row * Dd))[tid] = r;
}

// ================= launch =================
extern "C" void kernel_launch(void* const* d_in, const int* in_sizes, int n_in,
                              void* d_out, int out_size)
{
    const float* x     = (const float*)d_in[0];
    const int*   adj   = (const int*)d_in[1];
    const float* Wq    = (const float*)d_in[2];
    const float* bq    = (const float*)d_in[3];
    const float* Wk    = (const float*)d_in[4];
    const float* bk    = (const float*)d_in[5];
    const float* Wv    = (const float*)d_in[6];
    const float* bv    = (const float*)d_in[7];
    const float* Wo    = (const float*)d_in[8];
    const float* bo    = (const float*)d_in[9];
    const float* gamma = (const float*)d_in[10];
    const float* beta  = (const float*)d_in[11];
    float* out = (float*)d_out;

    float *Hb, *Yb, *Xr, *Wcat, *Wor, *bcat;
    __nv_bfloat16 *QKVh, *Vtp;
    uint32_t* Mbp;
    cudaGetSymbolAddress((void**)&QKVh, g_QKVh);
    cudaGetSymbolAddress((void**)&Vtp, g_Vt);
    cudaGetSymbolAddress((void**)&Hb, g_Hh);
    cudaGetSymbolAddress((void**)&Yb, g_Y);
    cudaGetSymbolAddress((void**)&Xr, g_Xr);
    cudaGetSymbolAddress((void**)&Wcat, g_Wcat);
    cudaGetSymbolAddress((void**)&Wor, g_Wor);
    cudaGetSymbolAddress((void**)&bcat, g_bcat);
    cudaGetSymbolAddress((void**)&Mbp, g_Mb);

    cudaFuncSetAttribute(attn_mma_kernel, cudaFuncAttributeMaxDynamicSharedMemorySize, ATTN_SMEM_BYTES);
    cudaFuncSetAttribute(gemm_mma_kernel, cudaFuncAttributeMaxDynamicSharedMemorySize, GEMM_SMEM_BYTES);

    pack_mask_kernel<<<(Mm * NW) / 256, 256>>>(adj, Mbp);
    round_kernel<<<(Mm * Dd / 4) / 256, 256>>>(x, Xr);
    round_kernel<<<(Dd * Dd / 4) / 256, 256>>>(Wo, Wor);
    pack_w_kernel<<<(Dd * QKS / 4) / 256, 256>>>(Wq, Wk, Wv, Wcat);
    pack_b_kernel<<<1, 384>>>(bq, bk, bv, bcat);

    // fused QKV projection -> bf16
    dim3 qgrid(QKS / GBN, Mm / GBM);   // (12, 64)
    gemm_mma_kernel<<<qgrid, 256, GEMM_SMEM_BYTES>>>(Xr, Wcat, bcat, nullptr, QKVh, Mm, QKS, Dd, 2);

    // V^T for attention
    dim3 tgrid(Nn / 64, Dd / 64, Bb);  // (32, 8, 4)
    transpose_v_kernel<<<tgrid, 256>>>(QKVh, Vtp);

    dim3 agrid(Nn / 128, Hh, Bb);      // (16, 8, 4)
    attn_mma_kernel<<<agrid, 256, ATTN_SMEM_BYTES>>>(QKVh, Vtp, Mbp, Hb);

    dim3 ogrid(Dd / GBN, Mm / GBM);    // (4, 64)
    gemm_mma_kernel<<<ogrid, 256, GEMM_SMEM_BYTES>>>(Hb, Wor, bo, x, Yb, Mm, Dd, Dd, 0);

    ln_kernel<<<Mm, 128>>>(Yb, gamma, beta, out);
}